// round 5
// baseline (speedup 1.0000x reference)
#include <cuda_runtime.h>

#define BB 2
#define NN 4096
#define CC 128
#define CIN 64
#define KK 16
#define GG 8
#define PPB (NN*KK)       // 65536 positions per batch
#define PP (BB*PPB)       // 131072 total positions
#define EPSF 1e-5f
#define CNTF 1048576.0f   // 16 * 4096 * 16 elements per (b,g)
#define SPITCH 136        // smem row pitch (floats): bank = 8*tig + gid -> conflict-free

// ---------------- scratch (device globals; no allocs allowed) ----------------
__device__ float g_f1T[BB*NN*CC];
__device__ float g_f2T[BB*NN*CC];
__device__ float g_g1T[BB*NN*CC];
__device__ float g_g2T[BB*NN*CC];
__device__ float g_fn1T[BB*NN*CC];
__device__ float g_fn2T[BB*NN*CC];
__device__ int   g_idx12[BB*NN*KK];
__device__ int   g_idx21[BB*NN*KK];
__device__ float g_dir12[BB*NN*KK*3];
__device__ float g_dir21[BB*NN*KK*3];
__device__ float g_bufA[CC*PP];      // channel-major [c][p]
__device__ float g_bufB[CC*PP];
__device__ float g_pool[BB*NN*CC];   // position-major [b][n][c]
__device__ float g_stats[8*BB*GG*2]; // per-stage (sum, sumsq)
__device__ float g_WT[3*CC*CC];      // transposed mlp weights: WT[c][o]

// ---------------- tf32 helpers ----------------------------------------------
__device__ __forceinline__ unsigned tf32h(float x){
    unsigned r; asm("cvt.rna.tf32.f32 %0, %1;" : "=r"(r) : "f"(x)); return r;
}
__device__ __forceinline__ void mma8(float* d, const unsigned* a, unsigned b0, unsigned b1){
    asm("mma.sync.aligned.m16n8k8.row.col.f32.tf32.tf32.f32 "
        "{%0,%1,%2,%3},{%4,%5,%6,%7},{%8,%9},{%0,%1,%2,%3};"
        : "+f"(d[0]),"+f"(d[1]),"+f"(d[2]),"+f"(d[3])
        : "r"(a[0]),"r"(a[1]),"r"(a[2]),"r"(a[3]), "r"(b0),"r"(b1));
}

// ---------------- input 1x1 convs: feat -> transposed features [b][n][c] ----
__global__ void k_conv1d_in(const float* __restrict__ feat1, const float* __restrict__ feat2,
                            const float* __restrict__ t11_w, const float* __restrict__ t11_b,
                            const float* __restrict__ t22_w, const float* __restrict__ t22_b) {
    int job = blockIdx.z;
    int b = blockIdx.y;
    int n0 = blockIdx.x * 32;
    const float* x    = (job==0||job==3) ? feat1 : feat2;
    const float* w    = (job==0||job==2) ? t11_w : t22_w;
    const float* bias = (job==0||job==2) ? t11_b : t22_b;
    float* outp = (job==0) ? g_f1T : (job==1) ? g_f2T : (job==2) ? g_g1T : g_g2T;

    __shared__ float xs[CIN*33];
    int t = threadIdx.x;   // 128
    for (int l=t; l<CIN*32; l+=128) {
        int c=l>>5, j=l&31;
        xs[c*33+j] = x[(b*CIN+c)*NN + n0+j];
    }
    __syncthreads();
    int o = t;
    float wr[CIN];
#pragma unroll
    for (int c=0;c<CIN;c++) wr[c] = w[o*CIN+c];
    float bv = bias[o];
    for (int j=0;j<32;j++){
        float acc = bv;
#pragma unroll
        for (int c=0;c<CIN;c++) acc += wr[c]*xs[c*33+j];
        outp[(b*NN+n0+j)*CC + o] = acc;
    }
}

// ---------------- KNN (k=16), broadcast version ------------------------------
__global__ void k_knn(const float* __restrict__ pc1, const float* __restrict__ pc2) {
    int dir = blockIdx.z;
    const float* pq   = (dir==0) ? pc1 : pc2;
    const float* pcnd = (dir==0) ? pc2 : pc1;
    int*   idxo = (dir==0) ? g_idx12 : g_idx21;
    float* diro = (dir==0) ? g_dir12 : g_dir21;
    int b = blockIdx.y;
    int n = blockIdx.x*128 + threadIdx.x;

    float qx = pq[(b*3+0)*NN+n], qy = pq[(b*3+1)*NN+n], qz = pq[(b*3+2)*NN+n];
    float s1 = qx*qx + qy*qy + qz*qz;

    float bd[KK]; int bi[KK];
#pragma unroll
    for (int k=0;k<KK;k++){ bd[k]=1e30f; bi[k]=0; }
    float worst = 1e30f;

    __shared__ float4 sc[512];
    for (int m0=0; m0<NN; m0+=512) {
        __syncthreads();
        for (int i=threadIdx.x; i<512; i+=128) {
            float x = pcnd[(b*3+0)*NN+m0+i];
            float y = pcnd[(b*3+1)*NN+m0+i];
            float z = pcnd[(b*3+2)*NN+m0+i];
            sc[i] = make_float4(x,y,z, x*x+y*y+z*z);
        }
        __syncthreads();
        for (int i=0;i<512;i++) {
            float4 c = sc[i];
            float d = s1 + c.w - 2.f*(qx*c.x + qy*c.y + qz*c.z);
            if (d < worst) {
                int j = KK-1;
                while (j>0 && bd[j-1] > d) { bd[j]=bd[j-1]; bi[j]=bi[j-1]; j--; }
                bd[j]=d; bi[j]=m0+i;
                worst = bd[KK-1];
            }
        }
    }
    for (int k=0;k<KK;k++){
        int m = bi[k];
        idxo[(b*NN+n)*KK+k] = m;
        float dx = pcnd[(b*3+0)*NN+m] - qx;
        float dy = pcnd[(b*3+1)*NN+m] - qy;
        float dz = pcnd[(b*3+2)*NN+m] - qz;
        diro[((b*NN+n)*KK+k)*3+0] = dx;
        diro[((b*NN+n)*KK+k)*3+1] = dy;
        diro[((b*NN+n)*KK+k)*3+2] = dz;
    }
}

// -------- weight transpose (m1a, m1b, m2a) + stats zeroing -------------------
__global__ void k_transw(const float* __restrict__ m1a, const float* __restrict__ m1b,
                         const float* __restrict__ m2a, float* __restrict__ stats) {
    if (blockIdx.x == 0) {
        for (int l=threadIdx.x; l<8*BB*GG*2; l+=256) stats[l] = 0.f;
    }
    const float* src = (blockIdx.x==0) ? m1a : (blockIdx.x==1) ? m1b : m2a;
    float* dst = g_WT + blockIdx.x*CC*CC;
    for (int l=threadIdx.x; l<CC*CC; l+=256){
        int o=l>>7, c=l&127;
        dst[c*CC+o] = src[l];
    }
}

// ---------------- gather prologue of a cross block ---------------------------
__global__ void k_gather(const int* __restrict__ idx, const float* __restrict__ dirv,
                         const float* __restrict__ p1T, const float* __restrict__ p2T,
                         const float* __restrict__ pos_w, const float* __restrict__ pos_b,
                         float* __restrict__ X, float* __restrict__ stats) {
    int b = blockIdx.y, n0 = blockIdx.x*8, c = threadIdx.x;
    float pw0 = pos_w[c*3+0], pw1 = pos_w[c*3+1], pw2 = pos_w[c*3+2], pb = pos_b[c];
    __shared__ float sh[CC*33];
    float sum=0.f, sq=0.f;
    int pbase = b*PPB + n0*KK;
    int lane = threadIdx.x & 31, r0 = threadIdx.x >> 5;

    for (int half=0; half<4; half++){
        for (int nn=0; nn<2; nn++){
            int n = n0 + half*2 + nn;
            float p1v = p1T[(b*NN+n)*CC + c];
            const int* ip = &idx[(b*NN+n)*KK];
            const float* dp0 = &dirv[(b*NN+n)*KK*3];
            for (int k=0;k<KK;k++){
                int m = ip[k];
                float pf = pw0*dp0[k*3+0] + pw1*dp0[k*3+1] + pw2*dp0[k*3+2] + pb;
                float v = p2T[(b*NN+m)*CC + c] + p1v + pf;
                sum += v; sq += v*v;
                sh[c*33 + nn*KK + k] = v;
            }
        }
        __syncthreads();
        int po = pbase + half*32;
        for (int r=r0; r<CC; r+=4)
            X[r*PP + po + lane] = sh[r*33 + lane];
        __syncthreads();
    }
#pragma unroll
    for (int off=8; off; off>>=1){
        sum += __shfl_down_sync(0xffffffffu, sum, off, 16);
        sq  += __shfl_down_sync(0xffffffffu, sq,  off, 16);
    }
    if ((threadIdx.x & 15)==0){
        int g = c >> 4;
        atomicAdd(&stats[(b*GG+g)*2+0], sum);
        atomicAdd(&stats[(b*GG+g)*2+1], sq);
    }
}

// ---- fused GN+LReLU(load) -> 3xTF32 tensor-core GEMM -> bias -> stats -------
// Y[o][p] = sum_c W[o][c] * lrelu(GN(X[c][p])) + bias[o]
__global__ void __launch_bounds__(256) k_gemm(const float* __restrict__ X,
        const float* __restrict__ WT, const float* __restrict__ bias,
        const float* __restrict__ statsIn, const float* __restrict__ gamma,
        const float* __restrict__ beta, float* __restrict__ Y,
        float* __restrict__ statsOut) {
    __shared__ unsigned Wh[16*SPITCH], Wl[16*SPITCH];
    __shared__ unsigned Xh[16*SPITCH], Xl[16*SPITCH];
    __shared__ float2 ssS[CC];

    int t = threadIdx.x;
    int pbase = blockIdx.x * 128;
    int b = pbase >> 16;
    if (t < CC) {
        int g = t >> 4;
        float s = statsIn[(b*GG+g)*2+0], q = statsIn[(b*GG+g)*2+1];
        float mu = s / CNTF;
        float var = q / CNTF - mu*mu;
        float rstd = rsqrtf(var + EPSF);
        float scale = rstd * gamma[t];
        ssS[t] = make_float2(scale, beta[t] - mu*scale);
    }
    __syncthreads();

    int lane = t & 31, w = t >> 5;
    int gid = lane >> 2, tig = lane & 3;
    int om = (w & 3) * 32;      // warp M (output-channel) base
    int pn = (w >> 2) * 64;     // warp N (position) base within the 128 tile

    float acc[2][8][4];
#pragma unroll
    for (int i=0;i<2;i++)
#pragma unroll
        for (int j=0;j<8;j++)
#pragma unroll
            for (int r=0;r<4;r++) acc[i][j][r]=0.f;

    for (int kc=0; kc<CC; kc+=16) {
#pragma unroll
        for (int i=0;i<8;i++){
            int l = t + i*256; int k = l>>7, p = l&127;
            float wv = WT[(kc+k)*CC + p];
            unsigned h = tf32h(wv);
            Wh[k*SPITCH+p] = h;
            Wl[k*SPITCH+p] = tf32h(wv - __uint_as_float(h));
            float2 s = ssS[kc+k];
            float v = X[(kc+k)*PP + pbase + p]*s.x + s.y;
            v = (v>=0.f) ? v : 0.1f*v;
            unsigned h2 = tf32h(v);
            Xh[k*SPITCH+p] = h2;
            Xl[k*SPITCH+p] = tf32h(v - __uint_as_float(h2));
        }
        __syncthreads();
#pragma unroll
        for (int ks=0; ks<16; ks+=8){
            int r0 = (ks + tig)*SPITCH;
            int r4 = (ks + tig + 4)*SPITCH;
            unsigned ah[2][4], al[2][4];
#pragma unroll
            for (int tm=0;tm<2;tm++){
                int ob = om + tm*16 + gid;
                ah[tm][0] = Wh[r0 + ob];
                ah[tm][1] = Wh[r0 + ob + 8];
                ah[tm][2] = Wh[r4 + ob];
                ah[tm][3] = Wh[r4 + ob + 8];
                al[tm][0] = Wl[r0 + ob];
                al[tm][1] = Wl[r0 + ob + 8];
                al[tm][2] = Wl[r4 + ob];
                al[tm][3] = Wl[r4 + ob + 8];
            }
#pragma unroll
            for (int tn=0;tn<8;tn++){
                int pb = pn + tn*8 + gid;
                unsigned bh0 = Xh[r0 + pb], bh1 = Xh[r4 + pb];
                unsigned bl0 = Xl[r0 + pb], bl1 = Xl[r4 + pb];
#pragma unroll
                for (int tm=0;tm<2;tm++){
                    mma8(acc[tm][tn], ah[tm], bh0, bh1);
                    mma8(acc[tm][tn], al[tm], bh0, bh1);
                    mma8(acc[tm][tn], ah[tm], bl0, bl1);
                }
            }
        }
        __syncthreads();
    }

    // epilogue: bias, stores, GN stats
    float ssum[2] = {0.f, 0.f}, sq[2] = {0.f, 0.f};
#pragma unroll
    for (int tm=0;tm<2;tm++){
        int row0 = om + tm*16 + gid;
        float bv0 = bias[row0], bv1 = bias[row0+8];
#pragma unroll
        for (int tn=0;tn<8;tn++){
            float y0 = acc[tm][tn][0] + bv0;
            float y1 = acc[tm][tn][1] + bv0;
            float y2 = acc[tm][tn][2] + bv1;
            float y3 = acc[tm][tn][3] + bv1;
            ssum[tm] += (y0+y1)+(y2+y3);
            sq[tm]   += (y0*y0+y1*y1)+(y2*y2+y3*y3);
            int col = pbase + pn + tn*8 + tig*2;
            *(float2*)&Y[(size_t)row0*PP + col]     = make_float2(y0,y1);
            *(float2*)&Y[(size_t)(row0+8)*PP + col] = make_float2(y2,y3);
        }
    }
#pragma unroll
    for (int off=16; off; off>>=1){
        ssum[0] += __shfl_down_sync(0xffffffffu, ssum[0], off);
        sq[0]   += __shfl_down_sync(0xffffffffu, sq[0],   off);
        ssum[1] += __shfl_down_sync(0xffffffffu, ssum[1], off);
        sq[1]   += __shfl_down_sync(0xffffffffu, sq[1],   off);
    }
    if (lane == 0){
        int gb = (w & 3)*2;
        atomicAdd(&statsOut[(b*GG+gb)*2+0],   ssum[0]);
        atomicAdd(&statsOut[(b*GG+gb)*2+1],   sq[0]);
        atomicAdd(&statsOut[(b*GG+gb+1)*2+0], ssum[1]);
        atomicAdd(&statsOut[(b*GG+gb+1)*2+1], sq[1]);
    }
}

// ---------------- GN+LReLU apply + max-pool over K ---------------------------
__global__ void k_pool(const float* __restrict__ Y, const float* __restrict__ statsIn,
                       const float* __restrict__ gamma, const float* __restrict__ beta,
                       float* __restrict__ outPM, float* __restrict__ outCM) {
    int b = blockIdx.y, n0 = blockIdx.x*32, c = threadIdx.x;
    int g = c >> 4;
    float s = statsIn[(b*GG+g)*2+0], q = statsIn[(b*GG+g)*2+1];
    float mu = s / CNTF;
    float var = q / CNTF - mu*mu;
    float rstd = rsqrtf(var + EPSF);
    float scale = rstd * gamma[c];
    float shift = beta[c] - mu*scale;
    __shared__ float sh[CC*36];
    for (int nn=0; nn<32; nn++){
        const float4* yp = (const float4*)&Y[c*PP + b*PPB + (n0+nn)*KK];
        float mx = -1e30f;
#pragma unroll
        for (int qq=0;qq<4;qq++){
            float4 v4 = yp[qq];
            float vs[4] = {v4.x,v4.y,v4.z,v4.w};
#pragma unroll
            for (int u=0;u<4;u++){
                float v = vs[u]*scale + shift;
                v = (v>=0.f) ? v : 0.1f*v;
                mx = fmaxf(mx, v);
            }
        }
        if (outPM) outPM[(b*NN+n0+nn)*CC + c] = mx;
        sh[c*36+nn] = mx;
    }
    if (outCM){
        __syncthreads();
        int lane = threadIdx.x & 31, r0 = threadIdx.x >> 5;
        for (int r=r0; r<CC; r+=4)
            outCM[(b*CC+r)*NN + n0 + lane] = sh[r*36+lane];
    }
}

// ---------------- trailing 1x1 conv (t1 / t2) --------------------------------
__global__ void k_conv1d2(const float* __restrict__ pin, const float* __restrict__ w,
                          const float* __restrict__ bias, float* __restrict__ outCM,
                          float* __restrict__ fnT) {
    int b = blockIdx.y, n0 = blockIdx.x*32, o = threadIdx.x;
    __shared__ float xs[CC*36];
    for (int l=threadIdx.x; l<CC*32; l+=128){
        int nj = l>>7, c = l&127;
        xs[c*36+nj] = pin[(b*NN+n0+nj)*CC + c];
    }
    __syncthreads();
    float acc[32];
    float bv = bias[o];
#pragma unroll
    for (int j=0;j<32;j++) acc[j]=bv;
    for (int cc=0; cc<4; cc++){
        float wr[32];
#pragma unroll
        for (int c2=0;c2<32;c2++) wr[c2] = w[o*CC + cc*32 + c2];
#pragma unroll
        for (int c2=0;c2<32;c2++){
            const float* xrow = &xs[(cc*32+c2)*36];
            float wv = wr[c2];
#pragma unroll
            for (int j4=0;j4<8;j4++){
                float4 xv = *(const float4*)&xrow[j4*4];
                acc[j4*4+0]+=wv*xv.x; acc[j4*4+1]+=wv*xv.y;
                acc[j4*4+2]+=wv*xv.z; acc[j4*4+3]+=wv*xv.w;
            }
        }
    }
#pragma unroll
    for (int j=0;j<32;j++) fnT[(b*NN+n0+j)*CC + o] = acc[j];
    __syncthreads();
#pragma unroll
    for (int j=0;j<32;j++) xs[o*36+j] = acc[j];
    __syncthreads();
    int lane = threadIdx.x & 31, r0 = threadIdx.x >> 5;
    for (int r=r0; r<CC; r+=4)
        outCM[(b*CC+r)*NN + n0 + lane] = xs[r*36+lane];
}

// ---------------- host orchestration ----------------------------------------
extern "C" void kernel_launch(void* const* d_in, const int* in_sizes, int n_in,
                              void* d_out, int out_size) {
    const float* pc1     = (const float*)d_in[0];
    const float* pc2     = (const float*)d_in[1];
    const float* feat1   = (const float*)d_in[2];
    const float* feat2   = (const float*)d_in[3];
    const float* t11_w   = (const float*)d_in[4];
    const float* t11_b   = (const float*)d_in[5];
    const float* t22_w   = (const float*)d_in[6];
    const float* t22_b   = (const float*)d_in[7];
    const float* pos1_w  = (const float*)d_in[8];
    const float* pos1_b  = (const float*)d_in[9];
    const float* gn1_g   = (const float*)d_in[10];
    const float* gn1_b   = (const float*)d_in[11];
    const float* m1a_w   = (const float*)d_in[12];
    const float* m1a_b   = (const float*)d_in[13];
    const float* m1a_g   = (const float*)d_in[14];
    const float* m1a_beta= (const float*)d_in[15];
    const float* m1b_w   = (const float*)d_in[16];
    const float* m1b_b   = (const float*)d_in[17];
    const float* m1b_g   = (const float*)d_in[18];
    const float* m1b_beta= (const float*)d_in[19];
    const float* t1_w    = (const float*)d_in[20];
    const float* t1_b    = (const float*)d_in[21];
    const float* t2_w    = (const float*)d_in[22];
    const float* t2_b    = (const float*)d_in[23];
    const float* pos2_w  = (const float*)d_in[24];
    const float* pos2_b  = (const float*)d_in[25];
    const float* gn2_g   = (const float*)d_in[26];
    const float* gn2_b   = (const float*)d_in[27];
    const float* m2a_w   = (const float*)d_in[28];
    const float* m2a_b   = (const float*)d_in[29];
    const float* m2a_g   = (const float*)d_in[30];
    const float* m2a_beta= (const float*)d_in[31];
    float* out = (float*)d_out;

    float *f1T,*f2T,*g1T,*g2T,*fn1T,*fn2T,*bufA,*bufB,*poolb,*stats,*WT,*dir12,*dir21;
    int *idx12,*idx21;
    cudaGetSymbolAddress((void**)&f1T,  g_f1T);
    cudaGetSymbolAddress((void**)&f2T,  g_f2T);
    cudaGetSymbolAddress((void**)&g1T,  g_g1T);
    cudaGetSymbolAddress((void**)&g2T,  g_g2T);
    cudaGetSymbolAddress((void**)&fn1T, g_fn1T);
    cudaGetSymbolAddress((void**)&fn2T, g_fn2T);
    cudaGetSymbolAddress((void**)&idx12,g_idx12);
    cudaGetSymbolAddress((void**)&idx21,g_idx21);
    cudaGetSymbolAddress((void**)&dir12,g_dir12);
    cudaGetSymbolAddress((void**)&dir21,g_dir21);
    cudaGetSymbolAddress((void**)&bufA, g_bufA);
    cudaGetSymbolAddress((void**)&bufB, g_bufB);
    cudaGetSymbolAddress((void**)&poolb,g_pool);
    cudaGetSymbolAddress((void**)&stats,g_stats);
    cudaGetSymbolAddress((void**)&WT,   g_WT);

    const int STB = BB*GG*2;   // stats floats per stage

    k_conv1d_in<<<dim3(NN/32, BB, 4), 128>>>(feat1, feat2, t11_w, t11_b, t22_w, t22_b);
    k_knn<<<dim3(NN/128, BB, 2), 128>>>(pc1, pc2);
    k_transw<<<3, 256>>>(m1a_w, m1b_w, m2a_w, stats);

    // ---- cross 1: queries pc1, cands pc2, p1=f1, p2=f2 ----
    k_gather<<<dim3(NN/8, BB), 128>>>(idx12, dir12, f1T, f2T, pos1_w, pos1_b, bufA, stats+0*STB);
    k_gemm<<<PP/128, 256>>>(bufA, WT+0*CC*CC, m1a_b, stats+0*STB, gn1_g, gn1_b, bufB, stats+1*STB);
    k_gemm<<<PP/128, 256>>>(bufB, WT+1*CC*CC, m1b_b, stats+1*STB, m1a_g, m1a_beta, bufA, stats+2*STB);
    k_pool<<<dim3(NN/32, BB), 128>>>(bufA, stats+2*STB, m1b_g, m1b_beta, poolb, nullptr);
    k_conv1d2<<<dim3(NN/32, BB), 128>>>(poolb, t1_w, t1_b, out, fn1T);

    // ---- cross 2: queries pc2, cands pc1, p1=g1, p2=g2 ----
    k_gather<<<dim3(NN/8, BB), 128>>>(idx21, dir21, g1T, g2T, pos1_w, pos1_b, bufA, stats+3*STB);
    k_gemm<<<PP/128, 256>>>(bufA, WT+0*CC*CC, m1a_b, stats+3*STB, gn1_g, gn1_b, bufB, stats+4*STB);
    k_gemm<<<PP/128, 256>>>(bufB, WT+1*CC*CC, m1b_b, stats+4*STB, m1a_g, m1a_beta, bufA, stats+5*STB);
    k_pool<<<dim3(NN/32, BB), 128>>>(bufA, stats+5*STB, m1b_g, m1b_beta, poolb, nullptr);
    k_conv1d2<<<dim3(NN/32, BB), 128>>>(poolb, t2_w, t2_b, out + BB*CC*NN, fn2T);

    // ---- cross 3: queries pc1, cands pc2, p1=feat1_new, p2=feat2_new ----
    k_gather<<<dim3(NN/8, BB), 128>>>(idx12, dir12, fn1T, fn2T, pos2_w, pos2_b, bufA, stats+6*STB);
    k_gemm<<<PP/128, 256>>>(bufA, WT+2*CC*CC, m2a_b, stats+6*STB, gn2_g, gn2_b, bufB, stats+7*STB);
    k_pool<<<dim3(NN/32, BB), 128>>>(bufB, stats+7*STB, m2a_g, m2a_beta, nullptr, out + 2*BB*CC*NN);
}

// round 6
// speedup vs baseline: 1.1573x; 1.1573x over previous
#include <cuda_runtime.h>

#define BB 2
#define NN 4096
#define CC 128
#define CIN 64
#define KK 16
#define GG 8
#define PPB (NN*KK)       // 65536 positions per batch
#define PP (BB*PPB)       // 131072 total positions
#define EPSF 1e-5f
#define CNTF 1048576.0f   // 16 * 4096 * 16 elements per (b,g)

// ---------------- scratch (device globals; no allocs allowed) ----------------
__device__ float g_f1T[BB*NN*CC];
__device__ float g_f2T[BB*NN*CC];
__device__ float g_g1T[BB*NN*CC];
__device__ float g_g2T[BB*NN*CC];
__device__ float g_fn1T[BB*NN*CC];
__device__ float g_fn2T[BB*NN*CC];
__device__ int   g_idx12[BB*NN*KK];
__device__ int   g_idx21[BB*NN*KK];
__device__ float g_dir12[BB*NN*KK*3];
__device__ float g_dir21[BB*NN*KK*3];
__device__ float g_bufA[CC*PP];      // channel-major [c][p]
__device__ float g_bufB[CC*PP];
__device__ float g_pool[BB*NN*CC];   // position-major [b][n][c]
__device__ float g_stats[8*BB*GG*2]; // per-stage (sum, sumsq)
__device__ float g_WT[3*CC*CC];      // transposed mlp weights: WT[c][o]

// ---------------- input 1x1 convs: feat -> transposed features [b][n][c] ----
__global__ void k_conv1d_in(const float* __restrict__ feat1, const float* __restrict__ feat2,
                            const float* __restrict__ t11_w, const float* __restrict__ t11_b,
                            const float* __restrict__ t22_w, const float* __restrict__ t22_b) {
    int job = blockIdx.z;
    int b = blockIdx.y;
    int n0 = blockIdx.x * 32;
    const float* x    = (job==0||job==3) ? feat1 : feat2;
    const float* w    = (job==0||job==2) ? t11_w : t22_w;
    const float* bias = (job==0||job==2) ? t11_b : t22_b;
    float* outp = (job==0) ? g_f1T : (job==1) ? g_f2T : (job==2) ? g_g1T : g_g2T;

    __shared__ float xs[CIN*33];
    int t = threadIdx.x;   // 128
    for (int l=t; l<CIN*32; l+=128) {
        int c=l>>5, j=l&31;
        xs[c*33+j] = x[(b*CIN+c)*NN + n0+j];
    }
    __syncthreads();
    int o = t;
    float wr[CIN];
#pragma unroll
    for (int c=0;c<CIN;c++) wr[c] = w[o*CIN+c];
    float bv = bias[o];
    for (int j=0;j<32;j++){
        float acc = bv;
#pragma unroll
        for (int c=0;c<CIN;c++) acc += wr[c]*xs[c*33+j];
        outp[(b*NN+n0+j)*CC + o] = acc;
    }
}

// ------- KNN (k=16): broadcast scan + STATIC-index register insertion --------
__global__ void k_knn(const float* __restrict__ pc1, const float* __restrict__ pc2) {
    int dir = blockIdx.z;
    const float* pq   = (dir==0) ? pc1 : pc2;
    const float* pcnd = (dir==0) ? pc2 : pc1;
    int*   idxo = (dir==0) ? g_idx12 : g_idx21;
    float* diro = (dir==0) ? g_dir12 : g_dir21;
    int b = blockIdx.y;
    int n = blockIdx.x*128 + threadIdx.x;

    float qx = pq[(b*3+0)*NN+n], qy = pq[(b*3+1)*NN+n], qz = pq[(b*3+2)*NN+n];
    float s1 = qx*qx + qy*qy + qz*qz;

    float bd[KK]; int bi[KK];     // sorted ascending; ALL accesses static-index
#pragma unroll
    for (int k=0;k<KK;k++){ bd[k]=1e30f; bi[k]=0; }
    float worst = 1e30f;

    __shared__ float4 sc[512];
    for (int m0=0; m0<NN; m0+=512) {
        __syncthreads();
        for (int i=threadIdx.x; i<512; i+=128) {
            float x = pcnd[(b*3+0)*NN+m0+i];
            float y = pcnd[(b*3+1)*NN+m0+i];
            float z = pcnd[(b*3+2)*NN+m0+i];
            sc[i] = make_float4(x,y,z, x*x+y*y+z*z);
        }
        __syncthreads();
#pragma unroll 4
        for (int i=0;i<512;i++) {
            float4 c = sc[i];
            float d = s1 + c.w - 2.f*(qx*c.x + qy*c.y + qz*c.z);
            if (d < worst) {
                int mi = m0 + i;
                // static compare-select insertion (no dynamic indexing -> no local mem)
                float nb[KK]; int ni[KK];
                bool c0 = bd[0] <= d;
                nb[0] = c0 ? bd[0] : d;
                ni[0] = c0 ? bi[0] : mi;
#pragma unroll
                for (int j=1;j<KK;j++){
                    bool cj  = bd[j]   <= d;
                    bool cjm = bd[j-1] <= d;
                    nb[j] = cj ? bd[j] : (cjm ? d : bd[j-1]);
                    ni[j] = cj ? bi[j] : (cjm ? mi : bi[j-1]);
                }
#pragma unroll
                for (int j=0;j<KK;j++){ bd[j]=nb[j]; bi[j]=ni[j]; }
                worst = bd[KK-1];
            }
        }
    }
#pragma unroll
    for (int k=0;k<KK;k++){
        int m = bi[k];
        idxo[(b*NN+n)*KK+k] = m;
        float dx = pcnd[(b*3+0)*NN+m] - qx;
        float dy = pcnd[(b*3+1)*NN+m] - qy;
        float dz = pcnd[(b*3+2)*NN+m] - qz;
        diro[((b*NN+n)*KK+k)*3+0] = dx;
        diro[((b*NN+n)*KK+k)*3+1] = dy;
        diro[((b*NN+n)*KK+k)*3+2] = dz;
    }
}

// -------- weight transpose (m1a, m1b, m2a) + stats zeroing -------------------
__global__ void k_transw(const float* __restrict__ m1a, const float* __restrict__ m1b,
                         const float* __restrict__ m2a, float* __restrict__ stats) {
    if (blockIdx.x == 0) {
        for (int l=threadIdx.x; l<8*BB*GG*2; l+=256) stats[l] = 0.f;
    }
    const float* src = (blockIdx.x==0) ? m1a : (blockIdx.x==1) ? m1b : m2a;
    float* dst = g_WT + blockIdx.x*CC*CC;
    for (int l=threadIdx.x; l<CC*CC; l+=256){
        int o=l>>7, c=l&127;
        dst[c*CC+o] = src[l];
    }
}

// ---------------- gather prologue of a cross block ---------------------------
__global__ void k_gather(const int* __restrict__ idx, const float* __restrict__ dirv,
                         const float* __restrict__ p1T, const float* __restrict__ p2T,
                         const float* __restrict__ pos_w, const float* __restrict__ pos_b,
                         float* __restrict__ X, float* __restrict__ stats) {
    int b = blockIdx.y, n0 = blockIdx.x*8, c = threadIdx.x;
    float pw0 = pos_w[c*3+0], pw1 = pos_w[c*3+1], pw2 = pos_w[c*3+2], pb = pos_b[c];
    __shared__ float sh[CC*33];
    float sum=0.f, sq=0.f;
    int pbase = b*PPB + n0*KK;
    int lane = threadIdx.x & 31, r0 = threadIdx.x >> 5;

    for (int half=0; half<4; half++){
        for (int nn=0; nn<2; nn++){
            int n = n0 + half*2 + nn;
            float p1v = p1T[(b*NN+n)*CC + c];
            const int* ip = &idx[(b*NN+n)*KK];
            const float* dp0 = &dirv[(b*NN+n)*KK*3];
            for (int k=0;k<KK;k++){
                int m = ip[k];
                float pf = pw0*dp0[k*3+0] + pw1*dp0[k*3+1] + pw2*dp0[k*3+2] + pb;
                float v = p2T[(b*NN+m)*CC + c] + p1v + pf;
                sum += v; sq += v*v;
                sh[c*33 + nn*KK + k] = v;
            }
        }
        __syncthreads();
        int po = pbase + half*32;
        for (int r=r0; r<CC; r+=4)
            X[r*PP + po + lane] = sh[r*33 + lane];
        __syncthreads();
    }
#pragma unroll
    for (int off=8; off; off>>=1){
        sum += __shfl_down_sync(0xffffffffu, sum, off, 16);
        sq  += __shfl_down_sync(0xffffffffu, sq,  off, 16);
    }
    if ((threadIdx.x & 15)==0){
        int g = c >> 4;
        atomicAdd(&stats[(b*GG+g)*2+0], sum);
        atomicAdd(&stats[(b*GG+g)*2+1], sq);
    }
}

// ---- fused GN+LReLU(load) -> scalar GEMM -> bias -> stats (R4 version) ------
__global__ void __launch_bounds__(256) k_gemm(const float* __restrict__ X,
        const float* __restrict__ WT, const float* __restrict__ bias,
        const float* __restrict__ statsIn, const float* __restrict__ gamma,
        const float* __restrict__ beta, float* __restrict__ Y,
        float* __restrict__ statsOut) {
    __shared__ float Ws[32*128];
    __shared__ float Xs[32*128];
    __shared__ float2 ssS[CC];
    int t = threadIdx.x;
    int pbase = blockIdx.x * 128;
    int b = pbase >> 16;
    if (t < CC) {
        int g = t >> 4;
        float s = statsIn[(b*GG+g)*2+0], q = statsIn[(b*GG+g)*2+1];
        float mu = s / CNTF;
        float var = q / CNTF - mu*mu;
        float rstd = rsqrtf(var + EPSF);
        float scale = rstd * gamma[t];
        ssS[t] = make_float2(scale, beta[t] - mu*scale);
    }

    float acc[8][8];
#pragma unroll
    for (int i=0;i<8;i++)
#pragma unroll
        for (int j=0;j<8;j++) acc[i][j]=0.f;

    int tx = t & 15, ty = t >> 4;
    for (int kc=0; kc<CC; kc+=32) {
        __syncthreads();
#pragma unroll
        for (int l=t; l<4096; l+=256) {
            int k=l>>7, o=l&127;
            Ws[l] = WT[(kc+k)*CC + o];
        }
#pragma unroll
        for (int l=t; l<4096; l+=256) {
            int k=l>>7, p=l&127;
            float2 s = ssS[kc+k];
            float v = X[(kc+k)*PP + pbase + p]*s.x + s.y;
            Xs[l] = (v>=0.f) ? v : 0.1f*v;
        }
        __syncthreads();
#pragma unroll
        for (int k=0;k<32;k++){
            float4 a0 = *(const float4*)&Ws[k*128 + ty*4];
            float4 a1 = *(const float4*)&Ws[k*128 + 64 + ty*4];
            float4 b0 = *(const float4*)&Xs[k*128 + tx*4];
            float4 b1 = *(const float4*)&Xs[k*128 + 64 + tx*4];
            float av[8] = {a0.x,a0.y,a0.z,a0.w,a1.x,a1.y,a1.z,a1.w};
            float bv[8] = {b0.x,b0.y,b0.z,b0.w,b1.x,b1.y,b1.z,b1.w};
#pragma unroll
            for (int i=0;i<8;i++)
#pragma unroll
                for (int j=0;j<8;j++) acc[i][j] += av[i]*bv[j];
        }
    }

    float s1=0.f,q1=0.f,s2=0.f,q2=0.f;
#pragma unroll
    for (int i=0;i<8;i++){
        int o = (i<4) ? (ty*4+i) : (64 + ty*4 + (i-4));
        float bv = bias[o];
        float y[8];
#pragma unroll
        for (int j=0;j<8;j++){
            y[j] = acc[i][j] + bv;
            if (i<4){ s1 += y[j]; q1 += y[j]*y[j]; }
            else    { s2 += y[j]; q2 += y[j]*y[j]; }
        }
        *(float4*)&Y[o*PP + pbase + tx*4]      = make_float4(y[0],y[1],y[2],y[3]);
        *(float4*)&Y[o*PP + pbase + 64 + tx*4] = make_float4(y[4],y[5],y[6],y[7]);
    }
#pragma unroll
    for (int off=16; off; off>>=1){
        s1 += __shfl_down_sync(0xffffffffu, s1, off);
        q1 += __shfl_down_sync(0xffffffffu, q1, off);
        s2 += __shfl_down_sync(0xffffffffu, s2, off);
        q2 += __shfl_down_sync(0xffffffffu, q2, off);
    }
    if ((t & 31)==0){
        int g1 = (t>>5)>>1;
        atomicAdd(&statsOut[(b*GG+g1)*2+0],   s1);
        atomicAdd(&statsOut[(b*GG+g1)*2+1],   q1);
        atomicAdd(&statsOut[(b*GG+4+g1)*2+0], s2);
        atomicAdd(&statsOut[(b*GG+4+g1)*2+1], q2);
    }
}

// ---------------- GN+LReLU apply + max-pool over K ---------------------------
__global__ void k_pool(const float* __restrict__ Y, const float* __restrict__ statsIn,
                       const float* __restrict__ gamma, const float* __restrict__ beta,
                       float* __restrict__ outPM, float* __restrict__ outCM) {
    int b = blockIdx.y, n0 = blockIdx.x*32, c = threadIdx.x;
    int g = c >> 4;
    float s = statsIn[(b*GG+g)*2+0], q = statsIn[(b*GG+g)*2+1];
    float mu = s / CNTF;
    float var = q / CNTF - mu*mu;
    float rstd = rsqrtf(var + EPSF);
    float scale = rstd * gamma[c];
    float shift = beta[c] - mu*scale;
    __shared__ float sh[CC*36];
    for (int nn=0; nn<32; nn++){
        const float4* yp = (const float4*)&Y[c*PP + b*PPB + (n0+nn)*KK];
        float mx = -1e30f;
#pragma unroll
        for (int qq=0;qq<4;qq++){
            float4 v4 = yp[qq];
            float vs[4] = {v4.x,v4.y,v4.z,v4.w};
#pragma unroll
            for (int u=0;u<4;u++){
                float v = vs[u]*scale + shift;
                v = (v>=0.f) ? v : 0.1f*v;
                mx = fmaxf(mx, v);
            }
        }
        if (outPM) outPM[(b*NN+n0+nn)*CC + c] = mx;
        sh[c*36+nn] = mx;
    }
    if (outCM){
        __syncthreads();
        int lane = threadIdx.x & 31, r0 = threadIdx.x >> 5;
        for (int r=r0; r<CC; r+=4)
            outCM[(b*CC+r)*NN + n0 + lane] = sh[r*36+lane];
    }
}

// ---------------- trailing 1x1 conv (t1 / t2) --------------------------------
__global__ void k_conv1d2(const float* __restrict__ pin, const float* __restrict__ w,
                          const float* __restrict__ bias, float* __restrict__ outCM,
                          float* __restrict__ fnT) {
    int b = blockIdx.y, n0 = blockIdx.x*32, o = threadIdx.x;
    __shared__ float xs[CC*36];
    for (int l=threadIdx.x; l<CC*32; l+=128){
        int nj = l>>7, c = l&127;
        xs[c*36+nj] = pin[(b*NN+n0+nj)*CC + c];
    }
    __syncthreads();
    float acc[32];
    float bv = bias[o];
#pragma unroll
    for (int j=0;j<32;j++) acc[j]=bv;
    for (int cc=0; cc<4; cc++){
        float wr[32];
#pragma unroll
        for (int c2=0;c2<32;c2++) wr[c2] = w[o*CC + cc*32 + c2];
#pragma unroll
        for (int c2=0;c2<32;c2++){
            const float* xrow = &xs[(cc*32+c2)*36];
            float wv = wr[c2];
#pragma unroll
            for (int j4=0;j4<8;j4++){
                float4 xv = *(const float4*)&xrow[j4*4];
                acc[j4*4+0]+=wv*xv.x; acc[j4*4+1]+=wv*xv.y;
                acc[j4*4+2]+=wv*xv.z; acc[j4*4+3]+=wv*xv.w;
            }
        }
    }
#pragma unroll
    for (int j=0;j<32;j++) fnT[(b*NN+n0+j)*CC + o] = acc[j];
    __syncthreads();
#pragma unroll
    for (int j=0;j<32;j++) xs[o*36+j] = acc[j];
    __syncthreads();
    int lane = threadIdx.x & 31, r0 = threadIdx.x >> 5;
    for (int r=r0; r<CC; r+=4)
        outCM[(b*CC+r)*NN + n0 + lane] = xs[r*36+lane];
}

// ---------------- host orchestration ----------------------------------------
extern "C" void kernel_launch(void* const* d_in, const int* in_sizes, int n_in,
                              void* d_out, int out_size) {
    const float* pc1     = (const float*)d_in[0];
    const float* pc2     = (const float*)d_in[1];
    const float* feat1   = (const float*)d_in[2];
    const float* feat2   = (const float*)d_in[3];
    const float* t11_w   = (const float*)d_in[4];
    const float* t11_b   = (const float*)d_in[5];
    const float* t22_w   = (const float*)d_in[6];
    const float* t22_b   = (const float*)d_in[7];
    const float* pos1_w  = (const float*)d_in[8];
    const float* pos1_b  = (const float*)d_in[9];
    const float* gn1_g   = (const float*)d_in[10];
    const float* gn1_b   = (const float*)d_in[11];
    const float* m1a_w   = (const float*)d_in[12];
    const float* m1a_b   = (const float*)d_in[13];
    const float* m1a_g   = (const float*)d_in[14];
    const float* m1a_beta= (const float*)d_in[15];
    const float* m1b_w   = (const float*)d_in[16];
    const float* m1b_b   = (const float*)d_in[17];
    const float* m1b_g   = (const float*)d_in[18];
    const float* m1b_beta= (const float*)d_in[19];
    const float* t1_w    = (const float*)d_in[20];
    const float* t1_b    = (const float*)d_in[21];
    const float* t2_w    = (const float*)d_in[22];
    const float* t2_b    = (const float*)d_in[23];
    const float* pos2_w  = (const float*)d_in[24];
    const float* pos2_b  = (const float*)d_in[25];
    const float* gn2_g   = (const float*)d_in[26];
    const float* gn2_b   = (const float*)d_in[27];
    const float* m2a_w   = (const float*)d_in[28];
    const float* m2a_b   = (const float*)d_in[29];
    const float* m2a_g   = (const float*)d_in[30];
    const float* m2a_beta= (const float*)d_in[31];
    float* out = (float*)d_out;

    float *f1T,*f2T,*g1T,*g2T,*fn1T,*fn2T,*bufA,*bufB,*poolb,*stats,*WT,*dir12,*dir21;
    int *idx12,*idx21;
    cudaGetSymbolAddress((void**)&f1T,  g_f1T);
    cudaGetSymbolAddress((void**)&f2T,  g_f2T);
    cudaGetSymbolAddress((void**)&g1T,  g_g1T);
    cudaGetSymbolAddress((void**)&g2T,  g_g2T);
    cudaGetSymbolAddress((void**)&fn1T, g_fn1T);
    cudaGetSymbolAddress((void**)&fn2T, g_fn2T);
    cudaGetSymbolAddress((void**)&idx12,g_idx12);
    cudaGetSymbolAddress((void**)&idx21,g_idx21);
    cudaGetSymbolAddress((void**)&dir12,g_dir12);
    cudaGetSymbolAddress((void**)&dir21,g_dir21);
    cudaGetSymbolAddress((void**)&bufA, g_bufA);
    cudaGetSymbolAddress((void**)&bufB, g_bufB);
    cudaGetSymbolAddress((void**)&poolb,g_pool);
    cudaGetSymbolAddress((void**)&stats,g_stats);
    cudaGetSymbolAddress((void**)&WT,   g_WT);

    const int STB = BB*GG*2;   // stats floats per stage

    k_conv1d_in<<<dim3(NN/32, BB, 4), 128>>>(feat1, feat2, t11_w, t11_b, t22_w, t22_b);
    k_knn<<<dim3(NN/128, BB, 2), 128>>>(pc1, pc2);
    k_transw<<<3, 256>>>(m1a_w, m1b_w, m2a_w, stats);

    // ---- cross 1: queries pc1, cands pc2, p1=f1, p2=f2 ----
    k_gather<<<dim3(NN/8, BB), 128>>>(idx12, dir12, f1T, f2T, pos1_w, pos1_b, bufA, stats+0*STB);
    k_gemm<<<PP/128, 256>>>(bufA, WT+0*CC*CC, m1a_b, stats+0*STB, gn1_g, gn1_b, bufB, stats+1*STB);
    k_gemm<<<PP/128, 256>>>(bufB, WT+1*CC*CC, m1b_b, stats+1*STB, m1a_g, m1a_beta, bufA, stats+2*STB);
    k_pool<<<dim3(NN/32, BB), 128>>>(bufA, stats+2*STB, m1b_g, m1b_beta, poolb, nullptr);
    k_conv1d2<<<dim3(NN/32, BB), 128>>>(poolb, t1_w, t1_b, out, fn1T);

    // ---- cross 2: queries pc2, cands pc1, p1=g1, p2=g2 ----
    k_gather<<<dim3(NN/8, BB), 128>>>(idx21, dir21, g1T, g2T, pos1_w, pos1_b, bufA, stats+3*STB);
    k_gemm<<<PP/128, 256>>>(bufA, WT+0*CC*CC, m1a_b, stats+3*STB, gn1_g, gn1_b, bufB, stats+4*STB);
    k_gemm<<<PP/128, 256>>>(bufB, WT+1*CC*CC, m1b_b, stats+4*STB, m1a_g, m1a_beta, bufA, stats+5*STB);
    k_pool<<<dim3(NN/32, BB), 128>>>(bufA, stats+5*STB, m1b_g, m1b_beta, poolb, nullptr);
    k_conv1d2<<<dim3(NN/32, BB), 128>>>(poolb, t2_w, t2_b, out + BB*CC*NN, fn2T);

    // ---- cross 3: queries pc1, cands pc2, p1=feat1_new, p2=feat2_new ----
    k_gather<<<dim3(NN/8, BB), 128>>>(idx12, dir12, fn1T, fn2T, pos2_w, pos2_b, bufA, stats+6*STB);
    k_gemm<<<PP/128, 256>>>(bufA, WT+2*CC*CC, m2a_b, stats+6*STB, gn2_g, gn2_b, bufB, stats+7*STB);
    k_pool<<<dim3(NN/32, BB), 128>>>(bufB, stats+7*STB, m2a_g, m2a_beta, nullptr, out + 2*BB*CC*NN);
}

// round 7
// speedup vs baseline: 1.6584x; 1.4330x over previous
#include <cuda_runtime.h>
#include <cuda_bf16.h>

#define BB 2
#define NN 4096
#define CC 128
#define CIN 64
#define KK 16
#define GG 8
#define PPB (NN*KK)       // 65536 positions per batch
#define PP (BB*PPB)       // 131072 total positions
#define EPSF 1e-5f
#define CNTF 1048576.0f   // 16 * 4096 * 16 elements per (b,g)
#define UPITCH 136        // smem pair-row pitch (uint32): bank = 8*tig+gid, conflict-free

// ---------------- scratch (device globals; no allocs allowed) ----------------
__device__ float g_f1T[BB*NN*CC];
__device__ float g_f2T[BB*NN*CC];
__device__ float g_g1T[BB*NN*CC];
__device__ float g_g2T[BB*NN*CC];
__device__ float g_fn1T[BB*NN*CC];
__device__ float g_fn2T[BB*NN*CC];
__device__ int   g_idx12[BB*NN*KK];
__device__ int   g_idx21[BB*NN*KK];
__device__ float g_dir12[BB*NN*KK*3];
__device__ float g_dir21[BB*NN*KK*3];
__device__ float g_bufA[CC*PP];      // channel-major [c][p]
__device__ float g_bufB[CC*PP];
__device__ float g_pool[BB*NN*CC];   // position-major [b][n][c]
__device__ float g_stats[8*BB*GG*2]; // per-stage (sum, sumsq)
__device__ float g_WT[3*CC*CC];      // transposed mlp weights: WT[c][o]

// ---------------- helpers ----------------------------------------------------
__device__ __forceinline__ void bf16split(float v, unsigned short &h, unsigned short &l){
    __nv_bfloat16 hb = __float2bfloat16_rn(v);
    float hf = __bfloat162float(hb);
    __nv_bfloat16 lb = __float2bfloat16_rn(v - hf);
    h = *(unsigned short*)&hb;
    l = *(unsigned short*)&lb;
}
__device__ __forceinline__ unsigned pack2(unsigned short lo, unsigned short hi){
    return (unsigned)lo | ((unsigned)hi << 16);
}
__device__ __forceinline__ void mma16(float* d, const unsigned* a, unsigned b0, unsigned b1){
    asm("mma.sync.aligned.m16n8k16.row.col.f32.bf16.bf16.f32 "
        "{%0,%1,%2,%3},{%4,%5,%6,%7},{%8,%9},{%0,%1,%2,%3};"
        : "+f"(d[0]),"+f"(d[1]),"+f"(d[2]),"+f"(d[3])
        : "r"(a[0]),"r"(a[1]),"r"(a[2]),"r"(a[3]), "r"(b0),"r"(b1));
}

// ---------------- input 1x1 convs: feat -> transposed features [b][n][c] ----
__global__ void k_conv1d_in(const float* __restrict__ feat1, const float* __restrict__ feat2,
                            const float* __restrict__ t11_w, const float* __restrict__ t11_b,
                            const float* __restrict__ t22_w, const float* __restrict__ t22_b) {
    int job = blockIdx.z;
    int b = blockIdx.y;
    int n0 = blockIdx.x * 32;
    const float* x    = (job==0||job==3) ? feat1 : feat2;
    const float* w    = (job==0||job==2) ? t11_w : t22_w;
    const float* bias = (job==0||job==2) ? t11_b : t22_b;
    float* outp = (job==0) ? g_f1T : (job==1) ? g_f2T : (job==2) ? g_g1T : g_g2T;

    __shared__ float xs[CIN*33];
    int t = threadIdx.x;   // 128
    for (int l=t; l<CIN*32; l+=128) {
        int c=l>>5, j=l&31;
        xs[c*33+j] = x[(b*CIN+c)*NN + n0+j];
    }
    __syncthreads();
    int o = t;
    float wr[CIN];
#pragma unroll
    for (int c=0;c<CIN;c++) wr[c] = w[o*CIN+c];
    float bv = bias[o];
    for (int j=0;j<32;j++){
        float acc = bv;
#pragma unroll
        for (int c=0;c<CIN;c++) acc += wr[c]*xs[c*33+j];
        outp[(b*NN+n0+j)*CC + o] = acc;
    }
}

// ------- KNN (k=16): 2-half candidate split (per-warp uniform) + merge -------
__global__ void __launch_bounds__(128) k_knn(const float* __restrict__ pc1, const float* __restrict__ pc2) {
    int dir = blockIdx.z;
    const float* pq   = (dir==0) ? pc1 : pc2;
    const float* pcnd = (dir==0) ? pc2 : pc1;
    int*   idxo = (dir==0) ? g_idx12 : g_idx21;
    float* diro = (dir==0) ? g_dir12 : g_dir21;
    int b = blockIdx.y;
    int t = threadIdx.x;
    int h  = t >> 6;        // candidate half (warps 0-1: half 0; warps 2-3: half 1)
    int qi = t & 63;        // query within block
    int n = blockIdx.x*64 + qi;

    float qx = pq[(b*3+0)*NN+n], qy = pq[(b*3+1)*NN+n], qz = pq[(b*3+2)*NN+n];
    float s1 = qx*qx + qy*qy + qz*qz;

    float bd[KK]; int bi[KK];
#pragma unroll
    for (int k=0;k<KK;k++){ bd[k]=1e30f; bi[k]=0; }
    float worst = 1e30f;

    __shared__ float4 sc[1024];
    __shared__ float md[64*17];
    __shared__ int   mi[64*17];

    for (int r=0; r<4; r++) {
        __syncthreads();
        for (int i=t; i<1024; i+=128) {
            int hs = i >> 9;
            int m = hs*2048 + r*512 + (i & 511);
            float x = pcnd[(b*3+0)*NN+m];
            float y = pcnd[(b*3+1)*NN+m];
            float z = pcnd[(b*3+2)*NN+m];
            sc[i] = make_float4(x,y,z, x*x+y*y+z*z);
        }
        __syncthreads();
        int mbase = h*2048 + r*512;
        const float4* base = &sc[h*512];
#pragma unroll 4
        for (int i=0;i<512;i++) {
            float4 c = base[i];
            float d = s1 + c.w - 2.f*(qx*c.x + qy*c.y + qz*c.z);
            if (d < worst) {
                int miv = mbase + i;
                float nb[KK]; int ni[KK];
                bool c0 = bd[0] <= d;
                nb[0] = c0 ? bd[0] : d;
                ni[0] = c0 ? bi[0] : miv;
#pragma unroll
                for (int j=1;j<KK;j++){
                    bool cj  = bd[j]   <= d;
                    bool cjm = bd[j-1] <= d;
                    nb[j] = cj ? bd[j] : (cjm ? d : bd[j-1]);
                    ni[j] = cj ? bi[j] : (cjm ? miv : bi[j-1]);
                }
#pragma unroll
                for (int j=0;j<KK;j++){ bd[j]=nb[j]; bi[j]=ni[j]; }
                worst = bd[KK-1];
            }
        }
    }
    __syncthreads();
    // half-1 threads publish their lists
    if (h == 1){
#pragma unroll
        for (int k=0;k<KK;k++){ md[qi*17+k] = bd[k]; mi[qi*17+k] = bi[k]; }
    }
    __syncthreads();
    if (h == 0){
        // merge half-1's sorted list into ours (half-0 indices are lower; ties keep ours)
#pragma unroll
        for (int k=0;k<KK;k++){
            float d = md[qi*17+k];
            if (d < worst){
                int miv = mi[qi*17+k];
                float nb[KK]; int ni[KK];
                bool c0 = bd[0] <= d;
                nb[0] = c0 ? bd[0] : d;
                ni[0] = c0 ? bi[0] : miv;
#pragma unroll
                for (int j=1;j<KK;j++){
                    bool cj  = bd[j]   <= d;
                    bool cjm = bd[j-1] <= d;
                    nb[j] = cj ? bd[j] : (cjm ? d : bd[j-1]);
                    ni[j] = cj ? bi[j] : (cjm ? miv : bi[j-1]);
                }
#pragma unroll
                for (int j=0;j<KK;j++){ bd[j]=nb[j]; bi[j]=ni[j]; }
                worst = bd[KK-1];
            }
        }
#pragma unroll
        for (int k=0;k<KK;k++){
            int m = bi[k];
            idxo[(b*NN+n)*KK+k] = m;
            float dx = pcnd[(b*3+0)*NN+m] - qx;
            float dy = pcnd[(b*3+1)*NN+m] - qy;
            float dz = pcnd[(b*3+2)*NN+m] - qz;
            diro[((b*NN+n)*KK+k)*3+0] = dx;
            diro[((b*NN+n)*KK+k)*3+1] = dy;
            diro[((b*NN+n)*KK+k)*3+2] = dz;
        }
    }
}

// -------- weight transpose (m1a, m1b, m2a) + stats zeroing -------------------
__global__ void k_transw(const float* __restrict__ m1a, const float* __restrict__ m1b,
                         const float* __restrict__ m2a, float* __restrict__ stats) {
    if (blockIdx.x == 0) {
        for (int l=threadIdx.x; l<8*BB*GG*2; l+=256) stats[l] = 0.f;
    }
    const float* src = (blockIdx.x==0) ? m1a : (blockIdx.x==1) ? m1b : m2a;
    float* dst = g_WT + blockIdx.x*CC*CC;
    for (int l=threadIdx.x; l<CC*CC; l+=256){
        int o=l>>7, c=l&127;
        dst[c*CC+o] = src[l];
    }
}

// ---------------- gather prologue of a cross block ---------------------------
__global__ void k_gather(const int* __restrict__ idx, const float* __restrict__ dirv,
                         const float* __restrict__ p1T, const float* __restrict__ p2T,
                         const float* __restrict__ pos_w, const float* __restrict__ pos_b,
                         float* __restrict__ X, float* __restrict__ stats) {
    int b = blockIdx.y, n0 = blockIdx.x*8, c = threadIdx.x;
    float pw0 = pos_w[c*3+0], pw1 = pos_w[c*3+1], pw2 = pos_w[c*3+2], pb = pos_b[c];
    __shared__ float sh[CC*33];
    float sum=0.f, sq=0.f;
    int pbase = b*PPB + n0*KK;
    int lane = threadIdx.x & 31, r0 = threadIdx.x >> 5;

    for (int half=0; half<4; half++){
        for (int nn=0; nn<2; nn++){
            int n = n0 + half*2 + nn;
            float p1v = p1T[(b*NN+n)*CC + c];
            const int* ip = &idx[(b*NN+n)*KK];
            const float* dp0 = &dirv[(b*NN+n)*KK*3];
            for (int k=0;k<KK;k++){
                int m = ip[k];
                float pf = pw0*dp0[k*3+0] + pw1*dp0[k*3+1] + pw2*dp0[k*3+2] + pb;
                float v = p2T[(b*NN+m)*CC + c] + p1v + pf;
                sum += v; sq += v*v;
                sh[c*33 + nn*KK + k] = v;
            }
        }
        __syncthreads();
        int po = pbase + half*32;
        for (int r=r0; r<CC; r+=4)
            X[r*PP + po + lane] = sh[r*33 + lane];
        __syncthreads();
    }
#pragma unroll
    for (int off=8; off; off>>=1){
        sum += __shfl_down_sync(0xffffffffu, sum, off, 16);
        sq  += __shfl_down_sync(0xffffffffu, sq,  off, 16);
    }
    if ((threadIdx.x & 15)==0){
        int g = c >> 4;
        atomicAdd(&stats[(b*GG+g)*2+0], sum);
        atomicAdd(&stats[(b*GG+g)*2+1], sq);
    }
}

// ---- fused GN+LReLU(load) -> bf16 3-term mma GEMM -> bias -> stats ----------
// Y[o][p] = sum_c W[o][c] * lrelu(GN(X[c][p])) + bias[o]
__global__ void __launch_bounds__(256) k_gemm(const float* __restrict__ X,
        const float* __restrict__ WT, const float* __restrict__ bias,
        const float* __restrict__ statsIn, const float* __restrict__ gamma,
        const float* __restrict__ beta, float* __restrict__ Y,
        float* __restrict__ statsOut) {
    __shared__ unsigned Wh[8*UPITCH], Wl[8*UPITCH];
    __shared__ unsigned Xh[8*UPITCH], Xl[8*UPITCH];
    __shared__ float2 ssS[CC];

    int t = threadIdx.x;
    int pbase = blockIdx.x * 128;
    int b = pbase >> 16;
    if (t < CC) {
        int g = t >> 4;
        float s = statsIn[(b*GG+g)*2+0], q = statsIn[(b*GG+g)*2+1];
        float mu = s / CNTF;
        float var = q / CNTF - mu*mu;
        float rstd = rsqrtf(var + EPSF);
        float scale = rstd * gamma[t];
        ssS[t] = make_float2(scale, beta[t] - mu*scale);
    }
    __syncthreads();

    int lane = t & 31, w = t >> 5;
    int gid = lane >> 2, tig = lane & 3;
    int om = (w & 3) * 32;      // warp M (output-channel) base
    int pn = (w >> 2) * 64;     // warp N (position) base within the 128 tile

    float acc[2][8][4];
#pragma unroll
    for (int i=0;i<2;i++)
#pragma unroll
        for (int j=0;j<8;j++)
#pragma unroll
            for (int r=0;r<4;r++) acc[i][j][r]=0.f;

    for (int kc=0; kc<CC; kc+=16) {
        __syncthreads();
        // stage: 8 pair-rows x 128 cols for W and X, split into bf16 hi/lo
#pragma unroll
        for (int i=0;i<4;i++){
            int l = t + i*256;          // 0..1023
            int k2 = l>>7, col = l&127;
            int kk = kc + k2*2;
            float w0 = WT[kk*CC + col];
            float w1 = WT[(kk+1)*CC + col];
            unsigned short h0,l0,h1,l1;
            bf16split(w0, h0, l0);
            bf16split(w1, h1, l1);
            Wh[k2*UPITCH+col] = pack2(h0, h1);
            Wl[k2*UPITCH+col] = pack2(l0, l1);
            float2 s0 = ssS[kk], s1 = ssS[kk+1];
            float x0 = X[(size_t)kk*PP + pbase + col]*s0.x + s0.y;
            float x1 = X[(size_t)(kk+1)*PP + pbase + col]*s1.x + s1.y;
            x0 = (x0>=0.f) ? x0 : 0.1f*x0;
            x1 = (x1>=0.f) ? x1 : 0.1f*x1;
            bf16split(x0, h0, l0);
            bf16split(x1, h1, l1);
            Xh[k2*UPITCH+col] = pack2(h0, h1);
            Xl[k2*UPITCH+col] = pack2(l0, l1);
        }
        __syncthreads();

        unsigned ah[2][4], al[2][4];
#pragma unroll
        for (int tm=0;tm<2;tm++){
            int mrow = om + tm*16 + gid;
            ah[tm][0] = Wh[tig*UPITCH + mrow];
            ah[tm][1] = Wh[tig*UPITCH + mrow + 8];
            ah[tm][2] = Wh[(tig+4)*UPITCH + mrow];
            ah[tm][3] = Wh[(tig+4)*UPITCH + mrow + 8];
            al[tm][0] = Wl[tig*UPITCH + mrow];
            al[tm][1] = Wl[tig*UPITCH + mrow + 8];
            al[tm][2] = Wl[(tig+4)*UPITCH + mrow];
            al[tm][3] = Wl[(tig+4)*UPITCH + mrow + 8];
        }
#pragma unroll
        for (int tn=0;tn<8;tn++){
            int p = pn + tn*8 + gid;
            unsigned bh0 = Xh[tig*UPITCH + p];
            unsigned bh1 = Xh[(tig+4)*UPITCH + p];
            unsigned bl0 = Xl[tig*UPITCH + p];
            unsigned bl1 = Xl[(tig+4)*UPITCH + p];
#pragma unroll
            for (int tm=0;tm<2;tm++){
                mma16(acc[tm][tn], ah[tm], bh0, bh1);
                mma16(acc[tm][tn], al[tm], bh0, bh1);
                mma16(acc[tm][tn], ah[tm], bl0, bl1);
            }
        }
    }

    // epilogue: bias, stores, GN stats (layout verified in R5)
    float ssum[2] = {0.f, 0.f}, sq[2] = {0.f, 0.f};
#pragma unroll
    for (int tm=0;tm<2;tm++){
        int row0 = om + tm*16 + gid;
        float bv0 = bias[row0], bv1 = bias[row0+8];
#pragma unroll
        for (int tn=0;tn<8;tn++){
            float y0 = acc[tm][tn][0] + bv0;
            float y1 = acc[tm][tn][1] + bv0;
            float y2 = acc[tm][tn][2] + bv1;
            float y3 = acc[tm][tn][3] + bv1;
            ssum[tm] += (y0+y1)+(y2+y3);
            sq[tm]   += (y0*y0+y1*y1)+(y2*y2+y3*y3);
            int col = pbase + pn + tn*8 + tig*2;
            *(float2*)&Y[(size_t)row0*PP + col]     = make_float2(y0,y1);
            *(float2*)&Y[(size_t)(row0+8)*PP + col] = make_float2(y2,y3);
        }
    }
#pragma unroll
    for (int off=16; off; off>>=1){
        ssum[0] += __shfl_down_sync(0xffffffffu, ssum[0], off);
        sq[0]   += __shfl_down_sync(0xffffffffu, sq[0],   off);
        ssum[1] += __shfl_down_sync(0xffffffffu, ssum[1], off);
        sq[1]   += __shfl_down_sync(0xffffffffu, sq[1],   off);
    }
    if (lane == 0){
        int gb = (w & 3)*2;
        atomicAdd(&statsOut[(b*GG+gb)*2+0],   ssum[0]);
        atomicAdd(&statsOut[(b*GG+gb)*2+1],   sq[0]);
        atomicAdd(&statsOut[(b*GG+gb+1)*2+0], ssum[1]);
        atomicAdd(&statsOut[(b*GG+gb+1)*2+1], sq[1]);
    }
}

// ------- GN+LReLU apply + max-pool over K (coalesced, shfl reduce) -----------
__global__ void __launch_bounds__(128) k_pool(const float* __restrict__ Y,
                       const float* __restrict__ statsIn,
                       const float* __restrict__ gamma, const float* __restrict__ beta,
                       float* __restrict__ outPM, float* __restrict__ outCM) {
    int b = blockIdx.y;
    int t = threadIdx.x;
    int p0 = b*PPB + blockIdx.x*128;       // 8 n's = 128 positions
    int nb = blockIdx.x*8 + (t >> 4);      // n within batch
    int kk = t & 15;
    __shared__ float2 ssS[CC];
    if (t < CC){
        int g = t >> 4;
        float s = statsIn[(b*GG+g)*2+0], q = statsIn[(b*GG+g)*2+1];
        float mu = s / CNTF;
        float var = q / CNTF - mu*mu;
        float rstd = rsqrtf(var + EPSF);
        float scale = rstd * gamma[t];
        ssS[t] = make_float2(scale, beta[t] - mu*scale);
    }
    __syncthreads();
#pragma unroll 4
    for (int c=0;c<CC;c++){
        float2 ss = ssS[c];
        float v = Y[(size_t)c*PP + p0 + t]*ss.x + ss.y;
        v = (v>=0.f) ? v : 0.1f*v;
#pragma unroll
        for (int off=8; off; off>>=1)
            v = fmaxf(v, __shfl_xor_sync(0xffffffffu, v, off, 16));
        if (kk == 0){
            if (outPM) outPM[(b*NN+nb)*CC + c] = v;
            if (outCM) outCM[(b*CC+c)*NN + nb] = v;
        }
    }
}

// ---------------- trailing 1x1 conv (t1 / t2) --------------------------------
__global__ void k_conv1d2(const float* __restrict__ pin, const float* __restrict__ w,
                          const float* __restrict__ bias, float* __restrict__ outCM,
                          float* __restrict__ fnT) {
    int b = blockIdx.y, n0 = blockIdx.x*32, o = threadIdx.x;
    __shared__ float xs[CC*36];
    for (int l=threadIdx.x; l<CC*32; l+=128){
        int nj = l>>7, c = l&127;
        xs[c*36+nj] = pin[(b*NN+n0+nj)*CC + c];
    }
    __syncthreads();
    float acc[32];
    float bv = bias[o];
#pragma unroll
    for (int j=0;j<32;j++) acc[j]=bv;
    for (int cc=0; cc<4; cc++){
        float wr[32];
#pragma unroll
        for (int c2=0;c2<32;c2++) wr[c2] = w[o*CC + cc*32 + c2];
#pragma unroll
        for (int c2=0;c2<32;c2++){
            const float* xrow = &xs[(cc*32+c2)*36];
            float wv = wr[c2];
#pragma unroll
            for (int j4=0;j4<8;j4++){
                float4 xv = *(const float4*)&xrow[j4*4];
                acc[j4*4+0]+=wv*xv.x; acc[j4*4+1]+=wv*xv.y;
                acc[j4*4+2]+=wv*xv.z; acc[j4*4+3]+=wv*xv.w;
            }
        }
    }
#pragma unroll
    for (int j=0;j<32;j++) fnT[(b*NN+n0+j)*CC + o] = acc[j];
    __syncthreads();
#pragma unroll
    for (int j=0;j<32;j++) xs[o*36+j] = acc[j];
    __syncthreads();
    int lane = threadIdx.x & 31, r0 = threadIdx.x >> 5;
    for (int r=r0; r<CC; r+=4)
        outCM[(b*CC+r)*NN + n0 + lane] = xs[r*36+lane];
}

// ---------------- host orchestration ----------------------------------------
extern "C" void kernel_launch(void* const* d_in, const int* in_sizes, int n_in,
                              void* d_out, int out_size) {
    const float* pc1     = (const float*)d_in[0];
    const float* pc2     = (const float*)d_in[1];
    const float* feat1   = (const float*)d_in[2];
    const float* feat2   = (const float*)d_in[3];
    const float* t11_w   = (const float*)d_in[4];
    const float* t11_b   = (const float*)d_in[5];
    const float* t22_w   = (const float*)d_in[6];
    const float* t22_b   = (const float*)d_in[7];
    const float* pos1_w  = (const float*)d_in[8];
    const float* pos1_b  = (const float*)d_in[9];
    const float* gn1_g   = (const float*)d_in[10];
    const float* gn1_b   = (const float*)d_in[11];
    const float* m1a_w   = (const float*)d_in[12];
    const float* m1a_b   = (const float*)d_in[13];
    const float* m1a_g   = (const float*)d_in[14];
    const float* m1a_beta= (const float*)d_in[15];
    const float* m1b_w   = (const float*)d_in[16];
    const float* m1b_b   = (const float*)d_in[17];
    const float* m1b_g   = (const float*)d_in[18];
    const float* m1b_beta= (const float*)d_in[19];
    const float* t1_w    = (const float*)d_in[20];
    const float* t1_b    = (const float*)d_in[21];
    const float* t2_w    = (const float*)d_in[22];
    const float* t2_b    = (const float*)d_in[23];
    const float* pos2_w  = (const float*)d_in[24];
    const float* pos2_b  = (const float*)d_in[25];
    const float* gn2_g   = (const float*)d_in[26];
    const float* gn2_b   = (const float*)d_in[27];
    const float* m2a_w   = (const float*)d_in[28];
    const float* m2a_b   = (const float*)d_in[29];
    const float* m2a_g   = (const float*)d_in[30];
    const float* m2a_beta= (const float*)d_in[31];
    float* out = (float*)d_out;

    float *f1T,*f2T,*g1T,*g2T,*fn1T,*fn2T,*bufA,*bufB,*poolb,*stats,*WT,*dir12,*dir21;
    int *idx12,*idx21;
    cudaGetSymbolAddress((void**)&f1T,  g_f1T);
    cudaGetSymbolAddress((void**)&f2T,  g_f2T);
    cudaGetSymbolAddress((void**)&g1T,  g_g1T);
    cudaGetSymbolAddress((void**)&g2T,  g_g2T);
    cudaGetSymbolAddress((void**)&fn1T, g_fn1T);
    cudaGetSymbolAddress((void**)&fn2T, g_fn2T);
    cudaGetSymbolAddress((void**)&idx12,g_idx12);
    cudaGetSymbolAddress((void**)&idx21,g_idx21);
    cudaGetSymbolAddress((void**)&dir12,g_dir12);
    cudaGetSymbolAddress((void**)&dir21,g_dir21);
    cudaGetSymbolAddress((void**)&bufA, g_bufA);
    cudaGetSymbolAddress((void**)&bufB, g_bufB);
    cudaGetSymbolAddress((void**)&poolb,g_pool);
    cudaGetSymbolAddress((void**)&stats,g_stats);
    cudaGetSymbolAddress((void**)&WT,   g_WT);

    const int STB = BB*GG*2;   // stats floats per stage

    k_conv1d_in<<<dim3(NN/32, BB, 4), 128>>>(feat1, feat2, t11_w, t11_b, t22_w, t22_b);
    k_knn<<<dim3(NN/64, BB, 2), 128>>>(pc1, pc2);
    k_transw<<<3, 256>>>(m1a_w, m1b_w, m2a_w, stats);

    // ---- cross 1: queries pc1, cands pc2, p1=f1, p2=f2 ----
    k_gather<<<dim3(NN/8, BB), 128>>>(idx12, dir12, f1T, f2T, pos1_w, pos1_b, bufA, stats+0*STB);
    k_gemm<<<PP/128, 256>>>(bufA, WT+0*CC*CC, m1a_b, stats+0*STB, gn1_g, gn1_b, bufB, stats+1*STB);
    k_gemm<<<PP/128, 256>>>(bufB, WT+1*CC*CC, m1b_b, stats+1*STB, m1a_g, m1a_beta, bufA, stats+2*STB);
    k_pool<<<dim3(NN/8, BB), 128>>>(bufA, stats+2*STB, m1b_g, m1b_beta, poolb, nullptr);
    k_conv1d2<<<dim3(NN/32, BB), 128>>>(poolb, t1_w, t1_b, out, fn1T);

    // ---- cross 2: queries pc2, cands pc1, p1=g1, p2=g2 ----
    k_gather<<<dim3(NN/8, BB), 128>>>(idx21, dir21, g1T, g2T, pos1_w, pos1_b, bufA, stats+3*STB);
    k_gemm<<<PP/128, 256>>>(bufA, WT+0*CC*CC, m1a_b, stats+3*STB, gn1_g, gn1_b, bufB, stats+4*STB);
    k_gemm<<<PP/128, 256>>>(bufB, WT+1*CC*CC, m1b_b, stats+4*STB, m1a_g, m1a_beta, bufA, stats+5*STB);
    k_pool<<<dim3(NN/8, BB), 128>>>(bufA, stats+5*STB, m1b_g, m1b_beta, poolb, nullptr);
    k_conv1d2<<<dim3(NN/32, BB), 128>>>(poolb, t2_w, t2_b, out + BB*CC*NN, fn2T);

    // ---- cross 3: queries pc1, cands pc2, p1=feat1_new, p2=feat2_new ----
    k_gather<<<dim3(NN/8, BB), 128>>>(idx12, dir12, fn1T, fn2T, pos2_w, pos2_b, bufA, stats+6*STB);
    k_gemm<<<PP/128, 256>>>(bufA, WT+2*CC*CC, m2a_b, stats+6*STB, gn2_g, gn2_b, bufB, stats+7*STB);
    k_pool<<<dim3(NN/8, BB), 128>>>(bufB, stats+7*STB, m2a_g, m2a_beta, nullptr, out + 2*BB*CC*NN);
}

// round 8
// speedup vs baseline: 1.7938x; 1.0816x over previous
#include <cuda_runtime.h>
#include <cuda_bf16.h>

#define BB 2
#define NN 4096
#define CC 128
#define CIN 64
#define KK 16
#define GG 8
#define PPB (NN*KK)       // 65536 positions per batch
#define PP (BB*PPB)       // 131072 positions per cross
#define POS (2*PP)        // merged cross1+cross2 position axis
#define EPSF 1e-5f
#define CNTF 1048576.0f   // 16 * 4096 * 16 elements per (cross,b,g)
#define UPITCH 136        // smem pair-row pitch (uint32), conflict-free
#define STW (2*BB*GG*2)   // stats floats per stage (2 crosses x B x G x 2)

// ---------------- scratch (device globals; no allocs allowed) ----------------
__device__ float g_f1T[BB*NN*CC];
__device__ float g_f2T[BB*NN*CC];
__device__ float g_g1T[BB*NN*CC];
__device__ float g_g2T[BB*NN*CC];
__device__ float g_fn1T[BB*NN*CC];
__device__ float g_fn2T[BB*NN*CC];
__device__ int   g_idx12[BB*NN*KK];
__device__ int   g_idx21[BB*NN*KK];
__device__ float g_dir12[BB*NN*KK*3];
__device__ float g_dir21[BB*NN*KK*3];
__device__ float g_bufA[CC*POS];     // channel-major [c][cross*PP + p]
__device__ float g_bufB[CC*POS];
__device__ float g_pool[2*BB*NN*CC]; // position-major, per cross
__device__ float g_stats[5*STW];     // per-stage (sum, sumsq)
__device__ unsigned g_Wh[3*64*128];  // packed bf16-hi pairs: [mat][kpair][orow]
__device__ unsigned g_Wl[3*64*128];  // packed bf16-lo pairs

// ---------------- helpers ----------------------------------------------------
__device__ __forceinline__ void bf16split(float v, unsigned short &h, unsigned short &l){
    __nv_bfloat16 hb = __float2bfloat16_rn(v);
    float hf = __bfloat162float(hb);
    __nv_bfloat16 lb = __float2bfloat16_rn(v - hf);
    h = *(unsigned short*)&hb;
    l = *(unsigned short*)&lb;
}
__device__ __forceinline__ unsigned pack2(unsigned short lo, unsigned short hi){
    return (unsigned)lo | ((unsigned)hi << 16);
}
__device__ __forceinline__ void mma16(float* d, const unsigned* a, unsigned b0, unsigned b1){
    asm("mma.sync.aligned.m16n8k16.row.col.f32.bf16.bf16.f32 "
        "{%0,%1,%2,%3},{%4,%5,%6,%7},{%8,%9},{%0,%1,%2,%3};"
        : "+f"(d[0]),"+f"(d[1]),"+f"(d[2]),"+f"(d[3])
        : "r"(a[0]),"r"(a[1]),"r"(a[2]),"r"(a[3]), "r"(b0),"r"(b1));
}

// ---------------- input 1x1 convs: feat -> transposed features [b][n][c] ----
__global__ void k_conv1d_in(const float* __restrict__ feat1, const float* __restrict__ feat2,
                            const float* __restrict__ t11_w, const float* __restrict__ t11_b,
                            const float* __restrict__ t22_w, const float* __restrict__ t22_b) {
    int job = blockIdx.z;
    int b = blockIdx.y;
    int n0 = blockIdx.x * 32;
    const float* x    = (job==0||job==3) ? feat1 : feat2;
    const float* w    = (job==0||job==2) ? t11_w : t22_w;
    const float* bias = (job==0||job==2) ? t11_b : t22_b;
    float* outp = (job==0) ? g_f1T : (job==1) ? g_f2T : (job==2) ? g_g1T : g_g2T;

    __shared__ float xs[CIN*33];
    int t = threadIdx.x;   // 128
    for (int l=t; l<CIN*32; l+=128) {
        int c=l>>5, j=l&31;
        xs[c*33+j] = x[(b*CIN+c)*NN + n0+j];
    }
    __syncthreads();
    int o = t;
    float wr[CIN];
#pragma unroll
    for (int c=0;c<CIN;c++) wr[c] = w[o*CIN+c];
    float bv = bias[o];
    for (int j=0;j<32;j++){
        float acc = bv;
#pragma unroll
        for (int c=0;c<CIN;c++) acc += wr[c]*xs[c*33+j];
        outp[(b*NN+n0+j)*CC + o] = acc;
    }
}

// ------- KNN (k=16): warp-granular 4-way candidate split + smem merge --------
__global__ void __launch_bounds__(128) k_knn(const float* __restrict__ pc1, const float* __restrict__ pc2) {
    int dir = blockIdx.z;
    const float* pq   = (dir==0) ? pc1 : pc2;
    const float* pcnd = (dir==0) ? pc2 : pc1;
    int*   idxo = (dir==0) ? g_idx12 : g_idx21;
    float* diro = (dir==0) ? g_dir12 : g_dir21;
    int b = blockIdx.y;
    int t = threadIdx.x;
    int q  = t >> 5;        // warp = candidate quarter
    int qi = t & 31;        // query within block (same across warps)
    int n = blockIdx.x*32 + qi;

    float qx = pq[(b*3+0)*NN+n], qy = pq[(b*3+1)*NN+n], qz = pq[(b*3+2)*NN+n];
    float s1 = qx*qx + qy*qy + qz*qz;

    float bd[KK]; int bi[KK];
#pragma unroll
    for (int k=0;k<KK;k++){ bd[k]=1e30f; bi[k]=0; }
    float worst = 1e30f;

    __shared__ float4 sc[1024];
    __shared__ float md[3*32*17];
    __shared__ int   mi[3*32*17];

    for (int r=0; r<4; r++) {
        __syncthreads();
        for (int i=t; i<1024; i+=128) {
            int hs = i >> 8;
            int m = hs*1024 + r*256 + (i & 255);
            float x = pcnd[(b*3+0)*NN+m];
            float y = pcnd[(b*3+1)*NN+m];
            float z = pcnd[(b*3+2)*NN+m];
            sc[i] = make_float4(x,y,z, x*x+y*y+z*z);
        }
        __syncthreads();
        int mbase = q*1024 + r*256;
        const float4* base = &sc[q*256];
#pragma unroll 4
        for (int i=0;i<256;i++) {
            float4 c = base[i];            // warp-broadcast read
            float d = s1 + c.w - 2.f*(qx*c.x + qy*c.y + qz*c.z);
            if (d < worst) {
                int miv = mbase + i;
                float nb[KK]; int ni[KK];
                bool c0 = bd[0] <= d;
                nb[0] = c0 ? bd[0] : d;
                ni[0] = c0 ? bi[0] : miv;
#pragma unroll
                for (int j=1;j<KK;j++){
                    bool cj  = bd[j]   <= d;
                    bool cjm = bd[j-1] <= d;
                    nb[j] = cj ? bd[j] : (cjm ? d : bd[j-1]);
                    ni[j] = cj ? bi[j] : (cjm ? miv : bi[j-1]);
                }
#pragma unroll
                for (int j=0;j<KK;j++){ bd[j]=nb[j]; bi[j]=ni[j]; }
                worst = bd[KK-1];
            }
        }
    }
    __syncthreads();
    if (q > 0){
#pragma unroll
        for (int k=0;k<KK;k++){
            md[((q-1)*32+qi)*17+k] = bd[k];
            mi[((q-1)*32+qi)*17+k] = bi[k];
        }
    }
    __syncthreads();
    if (q == 0){
        // merge quarters 1..3 in index order (ties keep lower-index entry)
        for (int s=0;s<3;s++){
#pragma unroll
            for (int k=0;k<KK;k++){
                float d = md[(s*32+qi)*17+k];
                if (d < worst){
                    int miv = mi[(s*32+qi)*17+k];
                    float nb[KK]; int ni[KK];
                    bool c0 = bd[0] <= d;
                    nb[0] = c0 ? bd[0] : d;
                    ni[0] = c0 ? bi[0] : miv;
#pragma unroll
                    for (int j=1;j<KK;j++){
                        bool cj  = bd[j]   <= d;
                        bool cjm = bd[j-1] <= d;
                        nb[j] = cj ? bd[j] : (cjm ? d : bd[j-1]);
                        ni[j] = cj ? bi[j] : (cjm ? miv : bi[j-1]);
                    }
#pragma unroll
                    for (int j=0;j<KK;j++){ bd[j]=nb[j]; bi[j]=ni[j]; }
                    worst = bd[KK-1];
                }
            }
        }
#pragma unroll
        for (int k=0;k<KK;k++){
            int m = bi[k];
            idxo[(b*NN+n)*KK+k] = m;
            float dx = pcnd[(b*3+0)*NN+m] - qx;
            float dy = pcnd[(b*3+1)*NN+m] - qy;
            float dz = pcnd[(b*3+2)*NN+m] - qz;
            diro[((b*NN+n)*KK+k)*3+0] = dx;
            diro[((b*NN+n)*KK+k)*3+1] = dy;
            diro[((b*NN+n)*KK+k)*3+2] = dz;
        }
    }
}

// -- weight prep: pack bf16 hi/lo k-pair fragments for m1a/m1b/m2a + zero stats
__global__ void k_transw(const float* __restrict__ m1a, const float* __restrict__ m1b,
                         const float* __restrict__ m2a, float* __restrict__ stats) {
    if (blockIdx.x == 0) {
        for (int l=threadIdx.x; l<5*STW; l+=256) stats[l] = 0.f;
    }
    const float* src = (blockIdx.x==0) ? m1a : (blockIdx.x==1) ? m1b : m2a;
    unsigned* dh = g_Wh + blockIdx.x*64*128;
    unsigned* dl = g_Wl + blockIdx.x*64*128;
    for (int l=threadIdx.x; l<64*128; l+=256){
        int kp = l >> 7, m = l & 127;
        float w0 = src[m*CC + 2*kp];
        float w1 = src[m*CC + 2*kp + 1];
        unsigned short h0,l0,h1,l1;
        bf16split(w0, h0, l0);
        bf16split(w1, h1, l1);
        dh[l] = pack2(h0, h1);
        dl[l] = pack2(l0, l1);
    }
}

// -------- gather prologue (merged: z = cross index selects pointer set) ------
__global__ void k_gather(const int* __restrict__ idxA, const float* __restrict__ dirA,
                         const float* __restrict__ p1A, const float* __restrict__ p2A,
                         const int* __restrict__ idxB, const float* __restrict__ dirB,
                         const float* __restrict__ p1B, const float* __restrict__ p2B,
                         const float* __restrict__ pos_w, const float* __restrict__ pos_b,
                         float* __restrict__ X, float* __restrict__ stats) {
    int cross = blockIdx.z;
    const int*   idx  = cross ? idxB : idxA;
    const float* dirv = cross ? dirB : dirA;
    const float* p1T  = cross ? p1B : p1A;
    const float* p2T  = cross ? p2B : p2A;
    int b = blockIdx.y, n0 = blockIdx.x*8, c = threadIdx.x;
    float pw0 = pos_w[c*3+0], pw1 = pos_w[c*3+1], pw2 = pos_w[c*3+2], pb = pos_b[c];
    __shared__ float sh[CC*33];
    float sum=0.f, sq=0.f;
    int pbase = cross*PP + b*PPB + n0*KK;
    int lane = threadIdx.x & 31, r0 = threadIdx.x >> 5;

    for (int half=0; half<4; half++){
        for (int nn=0; nn<2; nn++){
            int n = n0 + half*2 + nn;
            float p1v = p1T[(b*NN+n)*CC + c];
            const int* ip = &idx[(b*NN+n)*KK];
            const float* dp0 = &dirv[(b*NN+n)*KK*3];
            for (int k=0;k<KK;k++){
                int m = ip[k];
                float pf = pw0*dp0[k*3+0] + pw1*dp0[k*3+1] + pw2*dp0[k*3+2] + pb;
                float v = p2T[(b*NN+m)*CC + c] + p1v + pf;
                sum += v; sq += v*v;
                sh[c*33 + nn*KK + k] = v;
            }
        }
        __syncthreads();
        int po = pbase + half*32;
        for (int r=r0; r<CC; r+=4)
            X[(size_t)r*POS + po + lane] = sh[r*33 + lane];
        __syncthreads();
    }
#pragma unroll
    for (int off=8; off; off>>=1){
        sum += __shfl_down_sync(0xffffffffu, sum, off, 16);
        sq  += __shfl_down_sync(0xffffffffu, sq,  off, 16);
    }
    if ((threadIdx.x & 15)==0){
        int g = c >> 4;
        int slot = (cross*BB + b)*GG + g;
        atomicAdd(&stats[slot*2+0], sum);
        atomicAdd(&stats[slot*2+1], sq);
    }
}

// ---- fused GN+LReLU(load) -> bf16 3-term mma GEMM -> bias -> stats ----------
__global__ void __launch_bounds__(256) k_gemm(const float* __restrict__ X,
        const unsigned* __restrict__ Whp, const unsigned* __restrict__ Wlp,
        const float* __restrict__ bias,
        const float* __restrict__ statsIn, const float* __restrict__ gamma,
        const float* __restrict__ beta, float* __restrict__ Y,
        float* __restrict__ statsOut) {
    __shared__ unsigned Xh[8*UPITCH], Xl[8*UPITCH];
    __shared__ float2 ssS[CC];

    int t = threadIdx.x;
    int pbase = blockIdx.x * 128;
    int cross = pbase >> 17;
    int b = (pbase >> 16) & 1;
    int slotB = (cross*BB + b)*GG;
    if (t < CC) {
        int g = t >> 4;
        float s = statsIn[(slotB+g)*2+0], q = statsIn[(slotB+g)*2+1];
        float mu = s / CNTF;
        float var = q / CNTF - mu*mu;
        float rstd = rsqrtf(var + EPSF);
        float scale = rstd * gamma[t];
        ssS[t] = make_float2(scale, beta[t] - mu*scale);
    }
    __syncthreads();

    int lane = t & 31, w = t >> 5;
    int gid = lane >> 2, tig = lane & 3;
    int om = (w & 3) * 32;      // warp M (output-channel) base
    int pn = (w >> 2) * 64;     // warp N (position) base within the 128 tile

    float acc[2][8][4];
#pragma unroll
    for (int i=0;i<2;i++)
#pragma unroll
        for (int j=0;j<8;j++)
#pragma unroll
            for (int r=0;r<4;r++) acc[i][j][r]=0.f;

    for (int kc8=0; kc8<64; kc8+=8) {   // kc8 = k-pair base (8 pairs = 16 k per chunk)
        __syncthreads();
        // stage X chunk: 8 pair-rows x 128 cols, bf16 hi/lo split
#pragma unroll
        for (int i=0;i<4;i++){
            int l = t + i*256;          // 0..1023
            int k2 = l>>7, col = l&127;
            int kk = (kc8 + k2)*2;
            float2 s0 = ssS[kk], s1 = ssS[kk+1];
            float x0 = X[(size_t)kk*POS + pbase + col]*s0.x + s0.y;
            float x1 = X[(size_t)(kk+1)*POS + pbase + col]*s1.x + s1.y;
            x0 = (x0>=0.f) ? x0 : 0.1f*x0;
            x1 = (x1>=0.f) ? x1 : 0.1f*x1;
            unsigned short h0,l0,h1,l1;
            bf16split(x0, h0, l0);
            bf16split(x1, h1, l1);
            Xh[k2*UPITCH+col] = pack2(h0, h1);
            Xl[k2*UPITCH+col] = pack2(l0, l1);
        }
        __syncthreads();

        unsigned ah[2][4], al[2][4];
#pragma unroll
        for (int tm=0;tm<2;tm++){
            int mrow = om + tm*16 + gid;
            const unsigned* wh0 = &Whp[(kc8+tig)*128];
            const unsigned* wh4 = &Whp[(kc8+tig+4)*128];
            const unsigned* wl0 = &Wlp[(kc8+tig)*128];
            const unsigned* wl4 = &Wlp[(kc8+tig+4)*128];
            ah[tm][0] = __ldg(wh0 + mrow);
            ah[tm][1] = __ldg(wh0 + mrow + 8);
            ah[tm][2] = __ldg(wh4 + mrow);
            ah[tm][3] = __ldg(wh4 + mrow + 8);
            al[tm][0] = __ldg(wl0 + mrow);
            al[tm][1] = __ldg(wl0 + mrow + 8);
            al[tm][2] = __ldg(wl4 + mrow);
            al[tm][3] = __ldg(wl4 + mrow + 8);
        }
#pragma unroll
        for (int tn=0;tn<8;tn++){
            int p = pn + tn*8 + gid;
            unsigned bh0 = Xh[tig*UPITCH + p];
            unsigned bh1 = Xh[(tig+4)*UPITCH + p];
            unsigned bl0 = Xl[tig*UPITCH + p];
            unsigned bl1 = Xl[(tig+4)*UPITCH + p];
#pragma unroll
            for (int tm=0;tm<2;tm++){
                mma16(acc[tm][tn], ah[tm], bh0, bh1);
                mma16(acc[tm][tn], al[tm], bh0, bh1);
                mma16(acc[tm][tn], ah[tm], bl0, bl1);
            }
        }
    }

    // epilogue: bias, stores, GN stats
    float ssum[2] = {0.f, 0.f}, sq[2] = {0.f, 0.f};
#pragma unroll
    for (int tm=0;tm<2;tm++){
        int row0 = om + tm*16 + gid;
        float bv0 = bias[row0], bv1 = bias[row0+8];
#pragma unroll
        for (int tn=0;tn<8;tn++){
            float y0 = acc[tm][tn][0] + bv0;
            float y1 = acc[tm][tn][1] + bv0;
            float y2 = acc[tm][tn][2] + bv1;
            float y3 = acc[tm][tn][3] + bv1;
            ssum[tm] += (y0+y1)+(y2+y3);
            sq[tm]   += (y0*y0+y1*y1)+(y2*y2+y3*y3);
            int col = pbase + pn + tn*8 + tig*2;
            *(float2*)&Y[(size_t)row0*POS + col]     = make_float2(y0,y1);
            *(float2*)&Y[(size_t)(row0+8)*POS + col] = make_float2(y2,y3);
        }
    }
#pragma unroll
    for (int off=16; off; off>>=1){
        ssum[0] += __shfl_down_sync(0xffffffffu, ssum[0], off);
        sq[0]   += __shfl_down_sync(0xffffffffu, sq[0],   off);
        ssum[1] += __shfl_down_sync(0xffffffffu, ssum[1], off);
        sq[1]   += __shfl_down_sync(0xffffffffu, sq[1],   off);
    }
    if (lane == 0){
        int gb = (w & 3)*2;
        atomicAdd(&statsOut[(slotB+gb)*2+0],   ssum[0]);
        atomicAdd(&statsOut[(slotB+gb)*2+1],   sq[0]);
        atomicAdd(&statsOut[(slotB+gb+1)*2+0], ssum[1]);
        atomicAdd(&statsOut[(slotB+gb+1)*2+1], sq[1]);
    }
}

// ------- GN+LReLU apply + max-pool over K (coalesced, shfl reduce) -----------
__global__ void __launch_bounds__(128) k_pool(const float* __restrict__ Y,
                       const float* __restrict__ statsIn,
                       const float* __restrict__ gamma, const float* __restrict__ beta,
                       float* __restrict__ outPM0, float* __restrict__ outPM1,
                       float* __restrict__ outCM) {
    int cross = blockIdx.z;
    int b = blockIdx.y;
    int t = threadIdx.x;
    int p0 = cross*PP + b*PPB + blockIdx.x*128;
    int nb = blockIdx.x*8 + (t >> 4);
    int kk = t & 15;
    float* outPM = cross ? outPM1 : outPM0;
    int slotB = (cross*BB + b)*GG;
    __shared__ float2 ssS[CC];
    if (t < CC){
        int g = t >> 4;
        float s = statsIn[(slotB+g)*2+0], q = statsIn[(slotB+g)*2+1];
        float mu = s / CNTF;
        float var = q / CNTF - mu*mu;
        float rstd = rsqrtf(var + EPSF);
        float scale = rstd * gamma[t];
        ssS[t] = make_float2(scale, beta[t] - mu*scale);
    }
    __syncthreads();
#pragma unroll 4
    for (int c=0;c<CC;c++){
        float2 ss = ssS[c];
        float v = Y[(size_t)c*POS + p0 + t]*ss.x + ss.y;
        v = (v>=0.f) ? v : 0.1f*v;
#pragma unroll
        for (int off=8; off; off>>=1)
            v = fmaxf(v, __shfl_xor_sync(0xffffffffu, v, off, 16));
        if (kk == 0){
            if (outPM) outPM[(b*NN+nb)*CC + c] = v;
            if (outCM) outCM[(b*CC+c)*NN + nb] = v;
        }
    }
}

// ------- trailing 1x1 conv (merged t1/t2 via z) ------------------------------
__global__ void k_conv1d2(const float* __restrict__ poolb,
                          const float* __restrict__ t1_w, const float* __restrict__ t1_b,
                          const float* __restrict__ t2_w, const float* __restrict__ t2_b,
                          float* __restrict__ outBase, float* __restrict__ fn1T,
                          float* __restrict__ fn2T) {
    int z = blockIdx.z;
    const float* pin  = poolb + (size_t)z*BB*NN*CC;
    const float* w    = z ? t2_w : t1_w;
    const float* bias = z ? t2_b : t1_b;
    float* outCM = outBase + (size_t)z*BB*CC*NN;
    float* fnT   = z ? fn2T : fn1T;
    int b = blockIdx.y, n0 = blockIdx.x*32, o = threadIdx.x;
    __shared__ float xs[CC*36];
    for (int l=threadIdx.x; l<CC*32; l+=128){
        int nj = l>>7, c = l&127;
        xs[c*36+nj] = pin[(b*NN+n0+nj)*CC + c];
    }
    __syncthreads();
    float acc[32];
    float bv = bias[o];
#pragma unroll
    for (int j=0;j<32;j++) acc[j]=bv;
    for (int cc=0; cc<4; cc++){
        float wr[32];
#pragma unroll
        for (int c2=0;c2<32;c2++) wr[c2] = w[o*CC + cc*32 + c2];
#pragma unroll
        for (int c2=0;c2<32;c2++){
            const float* xrow = &xs[(cc*32+c2)*36];
            float wv = wr[c2];
#pragma unroll
            for (int j4=0;j4<8;j4++){
                float4 xv = *(const float4*)&xrow[j4*4];
                acc[j4*4+0]+=wv*xv.x; acc[j4*4+1]+=wv*xv.y;
                acc[j4*4+2]+=wv*xv.z; acc[j4*4+3]+=wv*xv.w;
            }
        }
    }
#pragma unroll
    for (int j=0;j<32;j++) fnT[(b*NN+n0+j)*CC + o] = acc[j];
    __syncthreads();
#pragma unroll
    for (int j=0;j<32;j++) xs[o*36+j] = acc[j];
    __syncthreads();
    int lane = threadIdx.x & 31, r0 = threadIdx.x >> 5;
    for (int r=r0; r<CC; r+=4)
        outCM[(b*CC+r)*NN + n0 + lane] = xs[r*36+lane];
}

// ---------------- host orchestration ----------------------------------------
extern "C" void kernel_launch(void* const* d_in, const int* in_sizes, int n_in,
                              void* d_out, int out_size) {
    const float* pc1     = (const float*)d_in[0];
    const float* pc2     = (const float*)d_in[1];
    const float* feat1   = (const float*)d_in[2];
    const float* feat2   = (const float*)d_in[3];
    const float* t11_w   = (const float*)d_in[4];
    const float* t11_b   = (const float*)d_in[5];
    const float* t22_w   = (const float*)d_in[6];
    const float* t22_b   = (const float*)d_in[7];
    const float* pos1_w  = (const float*)d_in[8];
    const float* pos1_b  = (const float*)d_in[9];
    const float* gn1_g   = (const float*)d_in[10];
    const float* gn1_b   = (const float*)d_in[11];
    const float* m1a_w   = (const float*)d_in[12];
    const float* m1a_b   = (const float*)d_in[13];
    const float* m1a_g   = (const float*)d_in[14];
    const float* m1a_beta= (const float*)d_in[15];
    const float* m1b_w   = (const float*)d_in[16];
    const float* m1b_b   = (const float*)d_in[17];
    const float* m1b_g   = (const float*)d_in[18];
    const float* m1b_beta= (const float*)d_in[19];
    const float* t1_w    = (const float*)d_in[20];
    const float* t1_b    = (const float*)d_in[21];
    const float* t2_w    = (const float*)d_in[22];
    const float* t2_b    = (const float*)d_in[23];
    const float* pos2_w  = (const float*)d_in[24];
    const float* pos2_b  = (const float*)d_in[25];
    const float* gn2_g   = (const float*)d_in[26];
    const float* gn2_b   = (const float*)d_in[27];
    const float* m2a_w   = (const float*)d_in[28];
    const float* m2a_b   = (const float*)d_in[29];
    const float* m2a_g   = (const float*)d_in[30];
    const float* m2a_beta= (const float*)d_in[31];
    float* out = (float*)d_out;

    float *f1T,*f2T,*g1T,*g2T,*fn1T,*fn2T,*bufA,*bufB,*poolb,*stats,*dir12,*dir21;
    unsigned *Wh,*Wl;
    int *idx12,*idx21;
    cudaGetSymbolAddress((void**)&f1T,  g_f1T);
    cudaGetSymbolAddress((void**)&f2T,  g_f2T);
    cudaGetSymbolAddress((void**)&g1T,  g_g1T);
    cudaGetSymbolAddress((void**)&g2T,  g_g2T);
    cudaGetSymbolAddress((void**)&fn1T, g_fn1T);
    cudaGetSymbolAddress((void**)&fn2T, g_fn2T);
    cudaGetSymbolAddress((void**)&idx12,g_idx12);
    cudaGetSymbolAddress((void**)&idx21,g_idx21);
    cudaGetSymbolAddress((void**)&dir12,g_dir12);
    cudaGetSymbolAddress((void**)&dir21,g_dir21);
    cudaGetSymbolAddress((void**)&bufA, g_bufA);
    cudaGetSymbolAddress((void**)&bufB, g_bufB);
    cudaGetSymbolAddress((void**)&poolb,g_pool);
    cudaGetSymbolAddress((void**)&stats,g_stats);
    cudaGetSymbolAddress((void**)&Wh,   g_Wh);
    cudaGetSymbolAddress((void**)&Wl,   g_Wl);

    k_conv1d_in<<<dim3(NN/32, BB, 4), 128>>>(feat1, feat2, t11_w, t11_b, t22_w, t22_b);
    k_knn<<<dim3(NN/32, BB, 2), 128>>>(pc1, pc2);
    k_transw<<<3, 256>>>(m1a_w, m1b_w, m2a_w, stats);

    // ---- cross1 + cross2 merged (shared weights pos1/gn1/mlp1) ----
    k_gather<<<dim3(NN/8, BB, 2), 128>>>(idx12, dir12, f1T, f2T,
                                         idx21, dir21, g1T, g2T,
                                         pos1_w, pos1_b, bufA, stats+0*STW);
    k_gemm<<<POS/128, 256>>>(bufA, Wh+0*64*128, Wl+0*64*128, m1a_b,
                             stats+0*STW, gn1_g, gn1_b, bufB, stats+1*STW);
    k_gemm<<<POS/128, 256>>>(bufB, Wh+1*64*128, Wl+1*64*128, m1b_b,
                             stats+1*STW, m1a_g, m1a_beta, bufA, stats+2*STW);
    k_pool<<<dim3(NN/8, BB, 2), 128>>>(bufA, stats+2*STW, m1b_g, m1b_beta,
                                       poolb, poolb + BB*NN*CC, nullptr);
    k_conv1d2<<<dim3(NN/32, BB, 2), 128>>>(poolb, t1_w, t1_b, t2_w, t2_b,
                                           out, fn1T, fn2T);

    // ---- cross 3: queries pc1, cands pc2, p1=feat1_new, p2=feat2_new ----
    k_gather<<<dim3(NN/8, BB, 1), 128>>>(idx12, dir12, fn1T, fn2T,
                                         idx12, dir12, fn1T, fn2T,
                                         pos2_w, pos2_b, bufA, stats+3*STW);
    k_gemm<<<PP/128, 256>>>(bufA, Wh+2*64*128, Wl+2*64*128, m2a_b,
                            stats+3*STW, gn2_g, gn2_b, bufB, stats+4*STW);
    k_pool<<<dim3(NN/8, BB, 1), 128>>>(bufB, stats+4*STW, m2a_g, m2a_beta,
                                       nullptr, nullptr, out + 2*BB*CC*NN);
}